// round 11
// baseline (speedup 1.0000x reference)
#include <cuda_runtime.h>
#include <cuda_bf16.h>
#include <cstdint>

// Feature gate: tcgen05 ops exist only in the sm_103a/sm_100a passes.
#if defined(__CUDA_ARCH__) && (defined(__CUDA_ARCH_FEAT_SM103_ALL) || defined(__CUDA_ARCH_FEAT_SM100_ALL))
#define USE_TC 1
#else
#define USE_TC 0
#endif

#define B_MAX  16384
#define TB     128
#define KD     3072
#define NGRP   8
#define KTILE  64          // bf16 K elements per stage (128 B/row = SW128)
#define NST    48          // KD / KTILE
#define RING   4
#define STG    40960       // xhi 16K + xlo 16K + bhi 4K + blo 4K
#define IDESC  0x8080490u  // kind::f16, bf16 x bf16 -> f32, M=128, N=32

// -------- device scratch --------
__device__ int g_counts[NGRP];
__device__ int g_cursor[NGRP];
__device__ int g_row_off[NGRP + 1];
__device__ int g_tile_off[NGRP + 1];
__device__ int g_perm[B_MAX];
// pre-split, pre-swizzled weights: [g][ktile][hi 4096B | lo 4096B]
__device__ __align__(16) unsigned char g_bw[NGRP * NST * 8192];

// -------- PTX helpers --------
__device__ __forceinline__ unsigned su32(const void* p) {
    return (unsigned)__cvta_generic_to_shared(p);
}
__device__ __forceinline__ void mbar_init(unsigned a, unsigned cnt) {
    asm volatile("mbarrier.init.shared.b64 [%0], %1;" :: "r"(a), "r"(cnt) : "memory");
}
__device__ __forceinline__ void mbar_wait(unsigned a, unsigned ph) {
    asm volatile(
        "{\n\t.reg .pred P;\n\t"
        "W_%=:\n\t"
        "mbarrier.try_wait.parity.acquire.cta.shared::cta.b64 P, [%0], %1, 0x989680;\n\t"
        "@P bra.uni D_%=;\n\t"
        "bra.uni W_%=;\n\t"
        "D_%=:\n\t}"
        :: "r"(a), "r"(ph) : "memory");
}
__device__ __forceinline__ void fence_async() {
    asm volatile("fence.proxy.async.shared::cta;" ::: "memory");
}
__device__ __forceinline__ unsigned long long mk_desc(unsigned addr) {
    const unsigned long long BASE =
        (2ull << 61) | (1ull << 46) | (64ull << 32) | (1ull << 16); // SW128,SBO=64,LBO=1
    return BASE | ((unsigned long long)(addr >> 4) & 0x3FFF);
}
__device__ __forceinline__ void mma_f16_ss(unsigned d, unsigned long long ad,
                                           unsigned long long bd, bool en) {
#if USE_TC
    unsigned e = en ? 1u : 0u;
    asm volatile(
        "{\n\t.reg .pred p;\n\t"
        "setp.ne.u32 p, %4, 0;\n\t"
        "tcgen05.mma.cta_group::1.kind::f16 [%0], %1, %2, %3, {%5, %5, %5, %5}, p;\n\t"
        "}"
        :: "r"(d), "l"(ad), "l"(bd), "r"(IDESC), "r"(e), "r"(0u) : "memory");
#endif
}
__device__ __forceinline__ void tc_commit(unsigned bar) {
#if USE_TC
    asm volatile(
        "tcgen05.commit.cta_group::1.mbarrier::arrive::one.shared::cluster.b64 [%0];"
        :: "r"(bar) : "memory");
#endif
}

// ============================================================================
// sort pipeline (warp-aggregated atomics)
// ============================================================================
__global__ void k_hist(const int* __restrict__ ls, int B) {
    int i = blockIdx.x * blockDim.x + threadIdx.x;
    int lane = threadIdx.x & 31;
    for (; i < B; i += gridDim.x * blockDim.x) {
        int g = ls[i];
        unsigned act = __activemask();
        if (act == 0xffffffffu) {
            unsigned m = __match_any_sync(0xffffffffu, g);
            if ((int)(__ffs(m) - 1) == lane) atomicAdd(&g_counts[g], __popc(m));
        } else {
            atomicAdd(&g_counts[g], 1);
        }
    }
}

__global__ void k_prefix() {
    if (threadIdx.x == 0 && blockIdx.x == 0) {
        int s = 0, t = 0;
        for (int g = 0; g < NGRP; g++) {
            g_row_off[g] = s;  g_tile_off[g] = t;  g_cursor[g] = s;
            s += g_counts[g];
            t += (g_counts[g] + TB - 1) / TB;
        }
        g_row_off[NGRP] = s;  g_tile_off[NGRP] = t;
    }
}

__global__ void k_scatter(const int* __restrict__ ls, int B) {
    int i = blockIdx.x * blockDim.x + threadIdx.x;
    int lane = threadIdx.x & 31;
    for (; i < B; i += gridDim.x * blockDim.x) {
        int g = ls[i];
        unsigned act = __activemask();
        if (act == 0xffffffffu) {
            unsigned m = __match_any_sync(0xffffffffu, g);
            int leader = __ffs(m) - 1;
            int rank = __popc(m & ((1u << lane) - 1u));
            int base = 0;
            if (lane == leader) base = atomicAdd(&g_cursor[g], __popc(m));
            base = __shfl_sync(0xffffffffu, base, leader);
            g_perm[base + rank] = i;
        } else {
            g_perm[atomicAdd(&g_cursor[g], 1)] = i;
        }
    }
}

// ============================================================================
// prep: split weights into bf16 hi/lo, pre-swizzled (SW128) per [g][ktile].
// Also zeroes the histogram counters (runs before k_hist).
// ============================================================================
__global__ void k_prep(const float* __restrict__ l1_w, const float* __restrict__ l1f_w) {
    if (blockIdx.x == 0 && threadIdx.x < NGRP) g_counts[threadIdx.x] = 0;
    int idx = blockIdx.x * blockDim.x + threadIdx.x;   // 8*48*32*32 = 393216
    if (idx >= NGRP * NST * 32 * 32) return;
    int kp  = idx & 31;
    int row = (idx >> 5) & 31;
    int kt  = (idx >> 10) % NST;
    int g   = (idx >> 10) / NST;
    int gk  = kt * KTILE + kp * 2;
    const float* src = (row < 16) ? (l1_w + (size_t)(g * 16 + row) * KD + gk)
                                  : (l1f_w + (size_t)(row - 16) * KD + gk);
    float w0 = src[0], w1 = src[1];
    __nv_bfloat162 h = __floats2bfloat162_rn(w0, w1);
    float2 hf = __bfloat1622float2(h);
    __nv_bfloat162 l = __floats2bfloat162_rn(w0 - hf.x, w1 - hf.y);
    unsigned off = row * 128 + kp * 4;
    off ^= (off >> 3) & 0x70;                       // SW128
    unsigned char* base = g_bw + (size_t)(g * NST + kt) * 8192;
    *(__nv_bfloat162*)(base + off)        = h;
    *(__nv_bfloat162*)(base + 4096 + off) = l;
}

// ============================================================================
// shared epilogue pieces
// ============================================================================
__device__ __forceinline__ void kan_stage(
    int tid, int g,
    const float* __restrict__ kan_grid, const float* __restrict__ kan_coef,
    const float* __restrict__ ksb,      const float* __restrict__ ksp,
    float* wsp, float* sbs, float* sgrid, float* srden)
{
    for (int t2 = tid; t2 < 5760; t2 += 256) {
        int k  = t2 % 6;
        int c  = (t2 / 6) & 31;
        int ii = t2 / 192;
        int id2 = ii * 256 + g * 32 + c;
        wsp[t2] = kan_coef[id2 * 6 + k] * ksp[id2];
    }
    for (int t2 = tid; t2 < 960; t2 += 256) {
        int c = t2 & 31, ii = t2 >> 5;
        sbs[t2] = ksb[ii * 256 + g * 32 + c];
    }
    for (int t2 = tid; t2 < 300; t2 += 256) sgrid[t2] = kan_grid[t2];
    for (int t2 = tid; t2 < 720; t2 += 256) {
        int ii = t2 / 24, j24 = t2 % 24;
        int d, j;
        if (j24 < 9)       { d = 1; j = j24; }
        else if (j24 < 17) { d = 2; j = j24 - 9; }
        else               { d = 3; j = j24 - 17; }
        const float* gr = kan_grid + ii * 10;
        srden[t2] = 1.0f / (gr[j + d] - gr[j]);
    }
}

__device__ __forceinline__ void kan_epilogue(
    int tid, int g, int nrows,
    const float* l1b, const float* wsp, const float* sbs,
    const float* sgrid, const float* srden, const float* sh_outw,
    const int* sh_rows, const float* __restrict__ out_b, float* __restrict__ out)
{
    const int r = tid >> 1, h = tid & 1;
    const float* lrow = l1b + r * 33;
    const float l1c_out = lrow[15];
    const float l1f_out = lrow[31];

    float a[30];
    #pragma unroll
    for (int i = 0; i < 15; i++) {
        float z = lrow[i] + lrow[16 + i];
        float q = (z * z) * (127.0f / 128.0f);
        a[i]      = fminf(fmaxf(q, 0.0f), 1.0f);
        a[i + 15] = fminf(fmaxf(z, 0.0f), 1.0f);
    }

    float acc2[16];
    #pragma unroll
    for (int c = 0; c < 16; c++) acc2[c] = 0.0f;

    #pragma unroll
    for (int i = 0; i < 30; i++) {
        const float* gr = sgrid + i * 10;
        const float* rd = srden + i * 24;
        const float xv  = a[i];

        float b[9];
        #pragma unroll
        for (int j = 0; j < 9; j++)
            b[j] = (xv >= gr[j] && xv < gr[j + 1]) ? 1.0f : 0.0f;
        #pragma unroll
        for (int d = 1; d <= 3; d++) {
            const float* rdd = rd + (d == 1 ? 0 : (d == 2 ? 9 : 17));
            #pragma unroll
            for (int j = 0; j <= 8 - d; j++)
                b[j] = (xv - gr[j]) * rdd[j] * b[j]
                     + (gr[j + d + 1] - xv) * rdd[j + 1] * b[j + 1];
        }
        const float sv = xv / (1.0f + __expf(-xv));

        const float* sbp = sbs + i * 32 + h * 16;
        const float* wp  = wsp + (i * 32 + h * 16) * 6;
        #pragma unroll
        for (int c = 0; c < 16; c++) {
            float tt = sv * sbp[c];
            #pragma unroll
            for (int k = 0; k < 6; k++)
                tt = fmaf(b[k], wp[c * 6 + k], tt);
            acc2[c] += tt;
        }
    }

    float part = 0.0f;
    #pragma unroll
    for (int c = 0; c < 16; c++) {
        float v = fminf(fmaxf(acc2[c], 0.0f), 1.0f);
        part = fmaf(v, sh_outw[h * 16 + c], part);
    }
    part += __shfl_xor_sync(0xffffffffu, part, 1);

    if (h == 0 && r < nrows)
        out[sh_rows[r]] = part + out_b[g] + l1f_out + l1c_out;
}

// ============================================================================
// main kernel
// ============================================================================
#define ARENA_BYTES (RING * STG + 47856 + 1024)

__global__ void __launch_bounds__(256, 1) k_main(
    const float* __restrict__ x,        const float* __restrict__ l1_b,
    const float* __restrict__ l1f_b,    const float* __restrict__ kan_grid,
    const float* __restrict__ kan_coef, const float* __restrict__ ksb,
    const float* __restrict__ ksp,      const float* __restrict__ out_w,
    const float* __restrict__ out_b,    float* __restrict__ out,
    const float* __restrict__ l1_w,     const float* __restrict__ l1f_w)
{
    extern __shared__ char raw[];
    __shared__ __align__(8) unsigned long long sh_empty[RING];
    __shared__ unsigned sh_tmem[1];
    __shared__ int   sh_rows[TB];
    __shared__ float sh_bias[32];
    __shared__ float sh_outw[32];

    const int bid = blockIdx.x, tid = threadIdx.x;

    int g = 0;
    #pragma unroll
    for (int i = 0; i < NGRP; i++)
        if (bid >= g_tile_off[i + 1]) g = i + 1;
    if (g >= NGRP) return;

    const int tile_in_g = bid - g_tile_off[g];
    const int row_start = g_row_off[g] + tile_in_g * TB;
    int nrows = g_row_off[g + 1] - row_start;
    if (nrows > TB) nrows = TB;

    if (tid < TB) {
        int rr = tid < nrows ? tid : (nrows - 1);
        sh_rows[tid] = g_perm[row_start + rr];
    }
    if (tid < 16)       sh_bias[tid] = l1_b[g * 16 + tid];
    else if (tid < 32)  sh_bias[tid] = l1f_b[tid - 16];
    if (tid < 32)       sh_outw[tid] = out_w[g * 32 + tid];

    char* base = (char*)(((uintptr_t)raw + 1023) & ~(uintptr_t)1023);

#if USE_TC
    // ======================= tensor-core path =======================
    if (tid == 0) {
        #pragma unroll
        for (int s = 0; s < RING; s++)
            mbar_init(su32(&sh_empty[s]), 1);
    }
    if (tid < 32) {
        asm volatile("tcgen05.alloc.cta_group::1.sync.aligned.shared::cta.b32 [%0], 64;"
                     :: "r"(su32(sh_tmem)) : "memory");
        asm volatile("tcgen05.relinquish_alloc_permit.cta_group::1.sync.aligned;");
    }
    __syncthreads();
    const unsigned tmem = sh_tmem[0];

    char* stg[RING];
    unsigned long long dxh[RING], dxl[RING], dbh[RING], dbl[RING];
    #pragma unroll
    for (int s = 0; s < RING; s++) {
        stg[s] = base + s * STG;
        dxh[s] = mk_desc(su32(stg[s]));
        dxl[s] = mk_desc(su32(stg[s] + 16384));
        dbh[s] = mk_desc(su32(stg[s] + 32768));
        dbl[s] = mk_desc(su32(stg[s] + 36864));
    }

    // ---- coalesced producer mapping ----
    // thread tid -> 8 rows (i*16 + tid/16), col bytes [(tid&15)*16, +16)
    // warp covers 2 rows x 256B contiguous -> 4 wavefronts per LDG.128.
    const int sub  = tid >> 4;
    const float* rptr[8];
    unsigned swoff[8];
    #pragma unroll
    for (int i = 0; i < 8; i++) {
        int row = i * 16 + sub;
        rptr[i] = x + (size_t)sh_rows[row] * KD + (tid & 15) * 4;
        unsigned off = (unsigned)(row * 128 + (tid & 15) * 8);  // bf16 bytes
        swoff[i] = off ^ ((off >> 3) & 0x70);                   // SW128
    }
    const unsigned char* bsrc = g_bw + (size_t)g * NST * 8192 + (size_t)tid * 16;

    // ---- 2-deep register prefetch (double buffer) ----
    float4 xf[2][8];
    uint4  bvh[2], bvl[2];
    #pragma unroll
    for (int i = 0; i < 8; i++) {
        xf[0][i] = *(const float4*)(rptr[i]);
        xf[1][i] = *(const float4*)(rptr[i] + KTILE);
    }
    bvh[0] = *(const uint4*)(bsrc);
    bvl[0] = *(const uint4*)(bsrc + 4096);
    bvh[1] = *(const uint4*)(bsrc + 8192);
    bvl[1] = *(const uint4*)(bsrc + 8192 + 4096);

    const int wid = tid >> 5, lid = tid & 31;

    int s = 0, pph = 1;
    bool en = false;

    for (int t = 0; t < NST; t++) {
        mbar_wait(su32(&sh_empty[s]), (unsigned)pph);

        const int pb = t & 1;
        char* xh = stg[s];
        char* xl = stg[s] + 16384;
        #pragma unroll
        for (int i = 0; i < 8; i++) {
            float4 f = xf[pb][i];
            __nv_bfloat162 h01 = __floats2bfloat162_rn(f.x, f.y);
            __nv_bfloat162 h23 = __floats2bfloat162_rn(f.z, f.w);
            float2 g01 = __bfloat1622float2(h01);
            float2 g23 = __bfloat1622float2(h23);
            __nv_bfloat162 l01 = __floats2bfloat162_rn(f.x - g01.x, f.y - g01.y);
            __nv_bfloat162 l23 = __floats2bfloat162_rn(f.z - g23.x, f.w - g23.y);
            *(uint2*)(xh + swoff[i]) = make_uint2(*(unsigned*)&h01, *(unsigned*)&h23);
            *(uint2*)(xl + swoff[i]) = make_uint2(*(unsigned*)&l01, *(unsigned*)&l23);
        }
        *(uint4*)(stg[s] + 32768 + tid * 16) = bvh[pb];
        *(uint4*)(stg[s] + 36864 + tid * 16) = bvl[pb];

        // prefetch stage t+2 into the buffer just freed (before fence/arrive)
        if (t + 2 < NST) {
            int k0 = (t + 2) * KTILE;
            #pragma unroll
            for (int i = 0; i < 8; i++) xf[pb][i] = *(const float4*)(rptr[i] + k0);
            bvh[pb] = *(const uint4*)(bsrc + (size_t)(t + 2) * 8192);
            bvl[pb] = *(const uint4*)(bsrc + (size_t)(t + 2) * 8192 + 4096);
        }

        fence_async();

        // split barrier: warps 1-7 arrive and run ahead; warp 0 collects,
        // then tid0 issues the MMAs for this stage and recycles the slot.
        if (wid == 0) {
            asm volatile("bar.sync %0, 256;" :: "r"(1 + s) : "memory");
            if (lid == 0) {
                #pragma unroll
                for (int ks = 0; ks < 4; ks++) {
                    unsigned long long o = (unsigned long long)(ks * 2);
                    mma_f16_ss(tmem, dxh[s] + o, dbh[s] + o, en); en = true;
                    mma_f16_ss(tmem, dxh[s] + o, dbl[s] + o, true);
                    mma_f16_ss(tmem, dxl[s] + o, dbh[s] + o, true);
                }
                tc_commit(su32(&sh_empty[s]));
            }
        } else {
            asm volatile("bar.arrive %0, 256;" :: "r"(1 + s) : "memory");
        }

        if (++s == RING) { s = 0; pph ^= 1; }
    }

    // stage KAN params while the tail MMAs drain
    float* l1b   = (float*)(base + RING * STG);
    float* wsp   = l1b + 4224;
    float* sbs   = wsp + 5760;
    float* sgrid = sbs + 960;
    float* srden = sgrid + 300;
    kan_stage(tid, g, kan_grid, kan_coef, ksb, ksp, wsp, sbs, sgrid, srden);

    // wait for the LAST stage's MMA group (same-accumulator MMAs complete in
    // order, so its commit implies all MMAs done).
    mbar_wait(su32(&sh_empty[(NST - 1) % RING]), (unsigned)pph);
    asm volatile("tcgen05.fence::after_thread_sync;" ::: "memory");

    if (wid < 4) {
        unsigned dr[32];
        asm volatile(
            "tcgen05.ld.sync.aligned.32x32b.x32.b32 "
            "{%0,%1,%2,%3,%4,%5,%6,%7,%8,%9,%10,%11,%12,%13,%14,%15,"
            "%16,%17,%18,%19,%20,%21,%22,%23,%24,%25,%26,%27,%28,%29,%30,%31}, [%32];"
            : "=r"(dr[0]), "=r"(dr[1]), "=r"(dr[2]), "=r"(dr[3]),
              "=r"(dr[4]), "=r"(dr[5]), "=r"(dr[6]), "=r"(dr[7]),
              "=r"(dr[8]), "=r"(dr[9]), "=r"(dr[10]), "=r"(dr[11]),
              "=r"(dr[12]), "=r"(dr[13]), "=r"(dr[14]), "=r"(dr[15]),
              "=r"(dr[16]), "=r"(dr[17]), "=r"(dr[18]), "=r"(dr[19]),
              "=r"(dr[20]), "=r"(dr[21]), "=r"(dr[22]), "=r"(dr[23]),
              "=r"(dr[24]), "=r"(dr[25]), "=r"(dr[26]), "=r"(dr[27]),
              "=r"(dr[28]), "=r"(dr[29]), "=r"(dr[30]), "=r"(dr[31])
            : "r"(tmem));
        asm volatile("tcgen05.wait::ld.sync.aligned;" ::: "memory");
        int row = wid * 32 + lid;
        #pragma unroll
        for (int c = 0; c < 32; c++)
            l1b[row * 33 + c] = __uint_as_float(dr[c]) + sh_bias[c];
        asm volatile("tcgen05.fence::before_thread_sync;" ::: "memory");
    }
    __syncthreads();

    kan_epilogue(tid, g, nrows, l1b, wsp, sbs, sgrid, srden,
                 sh_outw, sh_rows, out_b, out);

    __syncthreads();
    if (tid < 32) {
        asm volatile("tcgen05.dealloc.cta_group::1.sync.aligned.b32 %0, 64;"
                     :: "r"(tmem));
    }

#else
    // ======================= FP32 SIMT fallback =======================
    __syncthreads();
    float* xs = (float*)base;            // [128][33]
    float* ws = (float*)base + 4224;     // [32][33]

    const int tx = tid & 7;
    const int ty = tid >> 3;
    const int wid0 = tid >> 5;
    const int wk  = tid & 31;

    const float* wptr[4];
    #pragma unroll
    for (int it = 0; it < 4; it++) {
        int c = it * 8 + wid0;
        wptr[it] = (c < 16) ? (l1_w + (size_t)(g * 16 + c) * KD)
                            : (l1f_w + (size_t)(c - 16) * KD);
    }
    const float* xptr[4];
    int xr_[4], xkv[4];
    #pragma unroll
    for (int it = 0; it < 4; it++) {
        int idx = it * 256 + tid;
        xr_[it] = idx >> 3;
        xkv[it] = idx & 7;
        xptr[it] = x + (size_t)sh_rows[xr_[it]] * KD + xkv[it] * 4;
    }

    float4 xreg[4];
    float  wreg[4];
    #pragma unroll
    for (int it = 0; it < 4; it++) {
        xreg[it] = *(const float4*)(xptr[it]);
        wreg[it] = wptr[it][wk];
    }

    float acc[4][4];
    #pragma unroll
    for (int i = 0; i < 4; i++)
        #pragma unroll
        for (int j = 0; j < 4; j++) acc[i][j] = 0.0f;

    const int NT = KD / 32;
    for (int kt = 0; kt < NT; kt++) {
        __syncthreads();
        #pragma unroll
        for (int it = 0; it < 4; it++) {
            int bofs = xr_[it] * 33 + xkv[it] * 4;
            xs[bofs + 0] = xreg[it].x;  xs[bofs + 1] = xreg[it].y;
            xs[bofs + 2] = xreg[it].z;  xs[bofs + 3] = xreg[it].w;
            ws[(it * 8 + wid0) * 33 + wk] = wreg[it];
        }
        __syncthreads();
        if (kt + 1 < NT) {
            int k0 = (kt + 1) * 32;
            #pragma unroll
            for (int it = 0; it < 4; it++) {
                xreg[it] = *(const float4*)(xptr[it] + k0);
                wreg[it] = wptr[it][k0 + wk];
            }
        }
        #pragma unroll
        for (int kk = 0; kk < 32; kk++) {
            float xv[4], wv[4];
            #pragma unroll
            for (int j = 0; j < 4; j++) {
                xv[j] = xs[(4 * ty + j) * 33 + kk];
                wv[j] = ws[(4 * tx + j) * 33 + kk];
            }
            #pragma unroll
            for (int i = 0; i < 4; i++)
                #pragma unroll
                for (int j = 0; j < 4; j++)
                    acc[i][j] = fmaf(xv[i], wv[j], acc[i][j]);
        }
    }
    __syncthreads();

    #pragma unroll
    for (int i = 0; i < 4; i++)
        #pragma unroll
        for (int j = 0; j < 4; j++)
            xs[(4 * ty + i) * 33 + (4 * tx + j)] = acc[i][j] + sh_bias[4 * tx + j];

    float* l1b   = xs;
    float* wsp   = (float*)base + 4224;
    float* sbs   = wsp + 5760;
    float* sgrid = sbs + 960;
    float* srden = sgrid + 300;
    kan_stage(tid, g, kan_grid, kan_coef, ksb, ksp, wsp, sbs, sgrid, srden);
    __syncthreads();

    kan_epilogue(tid, g, nrows, l1b, wsp, sbs, sgrid, srden,
                 sh_outw, sh_rows, out_b, out);
#endif
}

// ============================================================================
extern "C" void kernel_launch(void* const* d_in, const int* in_sizes, int n_in,
                              void* d_out, int out_size)
{
    const float* x        = (const float*)d_in[0];
    const int*   ls       = (const int*)  d_in[1];
    const float* l1_w     = (const float*)d_in[2];
    const float* l1_b     = (const float*)d_in[3];
    const float* l1f_w    = (const float*)d_in[4];
    const float* l1f_b    = (const float*)d_in[5];
    const float* kan_grid = (const float*)d_in[6];
    const float* kan_coef = (const float*)d_in[7];
    const float* ksb      = (const float*)d_in[8];
    const float* ksp      = (const float*)d_in[9];
    const float* out_w    = (const float*)d_in[10];
    const float* out_b    = (const float*)d_in[11];
    float* out = (float*)d_out;

    int B = in_sizes[1];

    cudaFuncSetAttribute(k_main, cudaFuncAttributeMaxDynamicSharedMemorySize,
                         ARENA_BYTES);

    k_prep<<<(NGRP * NST * 32 * 32 + 255) / 256, 256>>>(l1_w, l1f_w);  // also zeroes counts
    k_hist<<<64, 256>>>(ls, B);
    k_prefix<<<1, 1>>>();
    k_scatter<<<64, 256>>>(ls, B);

    int tiles = B / TB + NGRP;
    k_main<<<tiles, 256, ARENA_BYTES>>>(x, l1_b, l1f_b, kan_grid,
                                        kan_coef, ksb, ksp, out_w, out_b, out,
                                        l1_w, l1f_w);
}

// round 12
// speedup vs baseline: 1.7116x; 1.7116x over previous
#include <cuda_runtime.h>
#include <cuda_bf16.h>
#include <cstdint>

// Feature gate: tcgen05 ops exist only in the sm_103a/sm_100a passes.
#if defined(__CUDA_ARCH__) && (defined(__CUDA_ARCH_FEAT_SM103_ALL) || defined(__CUDA_ARCH_FEAT_SM100_ALL))
#define USE_TC 1
#else
#define USE_TC 0
#endif

#define B_MAX  16384
#define TB     128
#define KD     3072
#define NGRP   8
#define KTILE  64          // bf16 K elements per stage (128 B/row = SW128)
#define NST    48          // KD / KTILE
#define RING   3
#define STG    40960       // xhi 16K + xlo 16K + bhi 4K + blo 4K
#define IDESC  0x8080490u  // kind::f16, bf16 x bf16 -> f32, M=128, N=32

// -------- device scratch (zero-initialized at module load) --------
__device__ int g_counts[NGRP];
__device__ int g_cursor[NGRP];
__device__ int g_row_off[NGRP + 1];
__device__ int g_tile_off[NGRP + 1];
__device__ int g_perm[B_MAX];
__device__ unsigned g_barctr;          // monotonic grid-barrier counter
// pre-split, pre-swizzled weights: [g][ktile][hi 4096B | lo 4096B]
__device__ __align__(16) unsigned char g_bw[NGRP * NST * 8192];

// -------- PTX helpers --------
__device__ __forceinline__ unsigned su32(const void* p) {
    return (unsigned)__cvta_generic_to_shared(p);
}
__device__ __forceinline__ void mbar_init(unsigned a, unsigned cnt) {
    asm volatile("mbarrier.init.shared.b64 [%0], %1;" :: "r"(a), "r"(cnt) : "memory");
}
__device__ __forceinline__ void mbar_wait(unsigned a, unsigned ph) {
    asm volatile(
        "{\n\t.reg .pred P;\n\t"
        "W_%=:\n\t"
        "mbarrier.try_wait.parity.acquire.cta.shared::cta.b64 P, [%0], %1, 0x989680;\n\t"
        "@P bra.uni D_%=;\n\t"
        "bra.uni W_%=;\n\t"
        "D_%=:\n\t}"
        :: "r"(a), "r"(ph) : "memory");
}
__device__ __forceinline__ void fence_async() {
    asm volatile("fence.proxy.async.shared::cta;" ::: "memory");
}
__device__ __forceinline__ unsigned long long mk_desc(unsigned addr) {
    const unsigned long long BASE =
        (2ull << 61) | (1ull << 46) | (64ull << 32) | (1ull << 16); // SW128,SBO=64,LBO=1
    return BASE | ((unsigned long long)(addr >> 4) & 0x3FFF);
}
__device__ __forceinline__ void mma_f16_ss(unsigned d, unsigned long long ad,
                                           unsigned long long bd, bool en) {
#if USE_TC
    unsigned e = en ? 1u : 0u;
    asm volatile(
        "{\n\t.reg .pred p;\n\t"
        "setp.ne.u32 p, %4, 0;\n\t"
        "tcgen05.mma.cta_group::1.kind::f16 [%0], %1, %2, %3, {%5, %5, %5, %5}, p;\n\t"
        "}"
        :: "r"(d), "l"(ad), "l"(bd), "r"(IDESC), "r"(e), "r"(0u) : "memory");
#endif
}
__device__ __forceinline__ void tc_commit(unsigned bar) {
#if USE_TC
    asm volatile(
        "tcgen05.commit.cta_group::1.mbarrier::arrive::one.shared::cluster.b64 [%0];"
        :: "r"(bar) : "memory");
#endif
}

// Software grid barrier — valid because grid (<=136 CTAs, 1 CTA/SM via 171KB
// smem) is fully co-resident on 148 SMs. Monotonic counter: no reset needed
// across graph replays, and consecutive barriers can't alias.
__device__ __forceinline__ void grid_barrier(int tid) {
    __syncthreads();
    if (tid == 0) {
        __threadfence();
        unsigned G = gridDim.x;
        unsigned old = atomicAdd(&g_barctr, 1u);
        unsigned target = (old / G + 1u) * G;
        while (*(volatile unsigned*)&g_barctr < target) { }
        __threadfence();
    }
    __syncthreads();
}

// ============================================================================
// shared epilogue pieces
// ============================================================================
__device__ __forceinline__ void kan_stage(
    int tid, int g,
    const float* __restrict__ kan_grid, const float* __restrict__ kan_coef,
    const float* __restrict__ ksb,      const float* __restrict__ ksp,
    float* wsp, float* sbs, float* sgrid, float* srden)
{
    for (int t2 = tid; t2 < 5760; t2 += 256) {
        int k  = t2 % 6;
        int c  = (t2 / 6) & 31;
        int ii = t2 / 192;
        int id2 = ii * 256 + g * 32 + c;
        wsp[t2] = kan_coef[id2 * 6 + k] * ksp[id2];
    }
    for (int t2 = tid; t2 < 960; t2 += 256) {
        int c = t2 & 31, ii = t2 >> 5;
        sbs[t2] = ksb[ii * 256 + g * 32 + c];
    }
    for (int t2 = tid; t2 < 300; t2 += 256) sgrid[t2] = kan_grid[t2];
    for (int t2 = tid; t2 < 720; t2 += 256) {
        int ii = t2 / 24, j24 = t2 % 24;
        int d, j;
        if (j24 < 9)       { d = 1; j = j24; }
        else if (j24 < 17) { d = 2; j = j24 - 9; }
        else               { d = 3; j = j24 - 17; }
        const float* gr = kan_grid + ii * 10;
        srden[t2] = 1.0f / (gr[j + d] - gr[j]);
    }
}

__device__ __forceinline__ void kan_epilogue(
    int tid, int g, int nrows,
    const float* l1b, const float* wsp, const float* sbs,
    const float* sgrid, const float* srden, const float* sh_outw,
    const int* sh_rows, const float* __restrict__ out_b, float* __restrict__ out)
{
    const int r = tid >> 1, h = tid & 1;
    const float* lrow = l1b + r * 33;
    const float l1c_out = lrow[15];
    const float l1f_out = lrow[31];

    float a[30];
    #pragma unroll
    for (int i = 0; i < 15; i++) {
        float z = lrow[i] + lrow[16 + i];
        float q = (z * z) * (127.0f / 128.0f);
        a[i]      = fminf(fmaxf(q, 0.0f), 1.0f);
        a[i + 15] = fminf(fmaxf(z, 0.0f), 1.0f);
    }

    float acc2[16];
    #pragma unroll
    for (int c = 0; c < 16; c++) acc2[c] = 0.0f;

    #pragma unroll
    for (int i = 0; i < 30; i++) {
        const float* gr = sgrid + i * 10;
        const float* rd = srden + i * 24;
        const float xv  = a[i];

        float b[9];
        #pragma unroll
        for (int j = 0; j < 9; j++)
            b[j] = (xv >= gr[j] && xv < gr[j + 1]) ? 1.0f : 0.0f;
        #pragma unroll
        for (int d = 1; d <= 3; d++) {
            const float* rdd = rd + (d == 1 ? 0 : (d == 2 ? 9 : 17));
            #pragma unroll
            for (int j = 0; j <= 8 - d; j++)
                b[j] = (xv - gr[j]) * rdd[j] * b[j]
                     + (gr[j + d + 1] - xv) * rdd[j + 1] * b[j + 1];
        }
        const float sv = xv / (1.0f + __expf(-xv));

        const float* sbp = sbs + i * 32 + h * 16;
        const float* wp  = wsp + (i * 32 + h * 16) * 6;
        #pragma unroll
        for (int c = 0; c < 16; c++) {
            float tt = sv * sbp[c];
            #pragma unroll
            for (int k = 0; k < 6; k++)
                tt = fmaf(b[k], wp[c * 6 + k], tt);
            acc2[c] += tt;
        }
    }

    float part = 0.0f;
    #pragma unroll
    for (int c = 0; c < 16; c++) {
        float v = fminf(fmaxf(acc2[c], 0.0f), 1.0f);
        part = fmaf(v, sh_outw[h * 16 + c], part);
    }
    part += __shfl_xor_sync(0xffffffffu, part, 1);

    if (h == 0 && r < nrows)
        out[sh_rows[r]] = part + out_b[g] + l1f_out + l1c_out;
}

// ============================================================================
// single fused kernel: sort + weight prep (phase 1, grid barriers) + R10 body
// ============================================================================
#define ARENA_BYTES (RING * STG + 47856 + 1024)

__global__ void __launch_bounds__(256, 1) k_main(
    const float* __restrict__ x,        const int* __restrict__ ls,
    const float* __restrict__ l1_w,     const float* __restrict__ l1_b,
    const float* __restrict__ l1f_w,    const float* __restrict__ l1f_b,
    const float* __restrict__ kan_grid, const float* __restrict__ kan_coef,
    const float* __restrict__ ksb,      const float* __restrict__ ksp,
    const float* __restrict__ out_w,    const float* __restrict__ out_b,
    float* __restrict__ out,            int B)
{
    extern __shared__ char raw[];
    __shared__ __align__(8) unsigned long long sh_empty[RING];
    __shared__ unsigned sh_tmem[1];
    __shared__ int   sh_rows[TB];
    __shared__ float sh_bias[32];
    __shared__ float sh_outw[32];

    const int bid = blockIdx.x, tid = threadIdx.x;
    const int gidx = bid * 256 + tid;
    const int nthr = (int)gridDim.x * 256;
    const int lane = tid & 31;

    // ================= phase 1: weight split + histogram =================
    for (int idx = gidx; idx < NGRP * NST * 32 * 32; idx += nthr) {
        int kp  = idx & 31;
        int row = (idx >> 5) & 31;
        int kt  = (idx >> 10) % NST;
        int g   = (idx >> 10) / NST;
        int gk  = kt * KTILE + kp * 2;
        const float* src = (row < 16) ? (l1_w + (size_t)(g * 16 + row) * KD + gk)
                                      : (l1f_w + (size_t)(row - 16) * KD + gk);
        float w0 = src[0], w1 = src[1];
        __nv_bfloat162 h = __floats2bfloat162_rn(w0, w1);
        float2 hf = __bfloat1622float2(h);
        __nv_bfloat162 l = __floats2bfloat162_rn(w0 - hf.x, w1 - hf.y);
        unsigned off = row * 128 + kp * 4;
        off ^= (off >> 3) & 0x70;                       // SW128
        unsigned char* bp = g_bw + (size_t)(g * NST + kt) * 8192;
        *(__nv_bfloat162*)(bp + off)        = h;
        *(__nv_bfloat162*)(bp + 4096 + off) = l;
    }
    int my_g = -1;
    if (gidx < B) {                     // B is a multiple of 32: warps uniform
        my_g = ls[gidx];
        unsigned m = __match_any_sync(0xffffffffu, my_g);
        if ((int)(__ffs(m) - 1) == lane) atomicAdd(&g_counts[my_g], __popc(m));
    }
    grid_barrier(tid);

    // prefix (block 0), then re-zero counts for the next graph replay
    if (bid == 0 && tid == 0) {
        int s = 0, t = 0;
        for (int g = 0; g < NGRP; g++) {
            g_row_off[g] = s;  g_tile_off[g] = t;  g_cursor[g] = s;
            s += g_counts[g];
            t += (g_counts[g] + TB - 1) / TB;
            g_counts[g] = 0;
        }
        g_row_off[NGRP] = s;  g_tile_off[NGRP] = t;
    }
    grid_barrier(tid);

    // scatter
    if (gidx < B) {
        unsigned m = __match_any_sync(0xffffffffu, my_g);
        int leader = __ffs(m) - 1;
        int rank = __popc(m & ((1u << lane) - 1u));
        int base0 = 0;
        if (lane == leader) base0 = atomicAdd(&g_cursor[my_g], __popc(m));
        base0 = __shfl_sync(0xffffffffu, base0, leader);
        g_perm[base0 + rank] = gidx;
    }
    grid_barrier(tid);

    // ================= phase 2: R10 tile body (unchanged) =================
    int g = 0;
    #pragma unroll
    for (int i = 0; i < NGRP; i++)
        if (bid >= g_tile_off[i + 1]) g = i + 1;
    if (g >= NGRP) return;   // whole block exits (all barriers already passed)

    const int tile_in_g = bid - g_tile_off[g];
    const int row_start = g_row_off[g] + tile_in_g * TB;
    int nrows = g_row_off[g + 1] - row_start;
    if (nrows > TB) nrows = TB;

    if (tid < TB) {
        int rr = tid < nrows ? tid : (nrows - 1);
        sh_rows[tid] = g_perm[row_start + rr];
    }
    if (tid < 16)       sh_bias[tid] = l1_b[g * 16 + tid];
    else if (tid < 32)  sh_bias[tid] = l1f_b[tid - 16];
    if (tid < 32)       sh_outw[tid] = out_w[g * 32 + tid];

    char* base = (char*)(((uintptr_t)raw + 1023) & ~(uintptr_t)1023);

#if USE_TC
    // ======================= tensor-core path =======================
    if (tid == 0) {
        #pragma unroll
        for (int s = 0; s < RING; s++)
            mbar_init(su32(&sh_empty[s]), 1);
    }
    if (tid < 32) {
        asm volatile("tcgen05.alloc.cta_group::1.sync.aligned.shared::cta.b32 [%0], 64;"
                     :: "r"(su32(sh_tmem)) : "memory");
        asm volatile("tcgen05.relinquish_alloc_permit.cta_group::1.sync.aligned;");
    }
    __syncthreads();
    const unsigned tmem = sh_tmem[0];

    char* stg[RING];
    unsigned long long dxh[RING], dxl[RING], dbh[RING], dbl[RING];
    #pragma unroll
    for (int s = 0; s < RING; s++) {
        stg[s] = base + s * STG;
        dxh[s] = mk_desc(su32(stg[s]));
        dxl[s] = mk_desc(su32(stg[s] + 16384));
        dbh[s] = mk_desc(su32(stg[s] + 32768));
        dbl[s] = mk_desc(su32(stg[s] + 36864));
    }

    // coalesced producer mapping: warp covers 2 rows x 256B -> 4 wavefronts
    const int sub  = tid >> 4;
    const float* rptr[8];
    unsigned swoff[8];
    #pragma unroll
    for (int i = 0; i < 8; i++) {
        int row = i * 16 + sub;
        rptr[i] = x + (size_t)sh_rows[row] * KD + (tid & 15) * 4;
        unsigned off = (unsigned)(row * 128 + (tid & 15) * 8);
        swoff[i] = off ^ ((off >> 3) & 0x70);
    }
    const unsigned char* bsrc = g_bw + (size_t)g * NST * 8192 + (size_t)tid * 16;

    float4 xf[8];
    uint4 bvh, bvl;
    #pragma unroll
    for (int i = 0; i < 8; i++) xf[i] = *(const float4*)(rptr[i]);
    bvh = *(const uint4*)(bsrc);
    bvl = *(const uint4*)(bsrc + 4096);

    int s = 0, pph = 1;
    bool en = false;

    for (int t = 0; t < NST; t++) {
        mbar_wait(su32(&sh_empty[s]), (unsigned)pph);

        char* xh = stg[s];
        char* xl = stg[s] + 16384;
        #pragma unroll
        for (int i = 0; i < 8; i++) {
            float4 f = xf[i];
            __nv_bfloat162 h01 = __floats2bfloat162_rn(f.x, f.y);
            __nv_bfloat162 h23 = __floats2bfloat162_rn(f.z, f.w);
            float2 g01 = __bfloat1622float2(h01);
            float2 g23 = __bfloat1622float2(h23);
            __nv_bfloat162 l01 = __floats2bfloat162_rn(f.x - g01.x, f.y - g01.y);
            __nv_bfloat162 l23 = __floats2bfloat162_rn(f.z - g23.x, f.w - g23.y);
            *(uint2*)(xh + swoff[i]) = make_uint2(*(unsigned*)&h01, *(unsigned*)&h23);
            *(uint2*)(xl + swoff[i]) = make_uint2(*(unsigned*)&l01, *(unsigned*)&l23);
        }
        *(uint4*)(stg[s] + 32768 + tid * 16) = bvh;
        *(uint4*)(stg[s] + 36864 + tid * 16) = bvl;

        fence_async();
        __syncthreads();                  // stage s image complete

        if (tid == 0) {
            #pragma unroll
            for (int ks = 0; ks < 4; ks++) {
                unsigned long long o = (unsigned long long)(ks * 2);
                mma_f16_ss(tmem, dxh[s] + o, dbh[s] + o, en); en = true;
                mma_f16_ss(tmem, dxh[s] + o, dbl[s] + o, true);
                mma_f16_ss(tmem, dxl[s] + o, dbh[s] + o, true);
            }
            tc_commit(su32(&sh_empty[s]));
        }

        if (t + 1 < NST) {                // prefetch next stage
            int k0 = (t + 1) * KTILE;
            #pragma unroll
            for (int i = 0; i < 8; i++) xf[i] = *(const float4*)(rptr[i] + k0);
            bvh = *(const uint4*)(bsrc + (size_t)(t + 1) * 8192);
            bvl = *(const uint4*)(bsrc + (size_t)(t + 1) * 8192 + 4096);
        }

        if (++s == RING) { s = 0; pph ^= 1; }
    }

    // stage KAN params while the tail MMAs drain
    float* l1b   = (float*)(base + RING * STG);
    float* wsp   = l1b + 4224;
    float* sbs   = wsp + 5760;
    float* sgrid = sbs + 960;
    float* srden = sgrid + 300;
    kan_stage(tid, g, kan_grid, kan_coef, ksb, ksp, wsp, sbs, sgrid, srden);

    // wait for the LAST stage's MMA group (same-accumulator MMAs complete in
    // order, so its commit implies all MMAs done).
    mbar_wait(su32(&sh_empty[(NST - 1) % RING]), (unsigned)pph);
    asm volatile("tcgen05.fence::after_thread_sync;" ::: "memory");

    const int wid = tid >> 5, lid = tid & 31;
    if (wid < 4) {
        unsigned dr[32];
        asm volatile(
            "tcgen05.ld.sync.aligned.32x32b.x32.b32 "
            "{%0,%1,%2,%3,%4,%5,%6,%7,%8,%9,%10,%11,%12,%13,%14,%15,"
            "%16,%17,%18,%19,%20,%21,%22,%23,%24,%25,%26,%27,%28,%29,%30,%31}, [%32];"
            : "=r"(dr[0]), "=r"(dr[1]), "=r"(dr[2]), "=r"(dr[3]),
              "=r"(dr[4]), "=r"(dr[5]), "=r"(dr[6]), "=r"(dr[7]),
              "=r"(dr[8]), "=r"(dr[9]), "=r"(dr[10]), "=r"(dr[11]),
              "=r"(dr[12]), "=r"(dr[13]), "=r"(dr[14]), "=r"(dr[15]),
              "=r"(dr[16]), "=r"(dr[17]), "=r"(dr[18]), "=r"(dr[19]),
              "=r"(dr[20]), "=r"(dr[21]), "=r"(dr[22]), "=r"(dr[23]),
              "=r"(dr[24]), "=r"(dr[25]), "=r"(dr[26]), "=r"(dr[27]),
              "=r"(dr[28]), "=r"(dr[29]), "=r"(dr[30]), "=r"(dr[31])
            : "r"(tmem));
        asm volatile("tcgen05.wait::ld.sync.aligned;" ::: "memory");
        int row = wid * 32 + lid;
        #pragma unroll
        for (int c = 0; c < 32; c++)
            l1b[row * 33 + c] = __uint_as_float(dr[c]) + sh_bias[c];
        asm volatile("tcgen05.fence::before_thread_sync;" ::: "memory");
    }
    __syncthreads();

    kan_epilogue(tid, g, nrows, l1b, wsp, sbs, sgrid, srden,
                 sh_outw, sh_rows, out_b, out);

    __syncthreads();
    if (tid < 32) {
        asm volatile("tcgen05.dealloc.cta_group::1.sync.aligned.b32 %0, 64;"
                     :: "r"(tmem));
    }

#else
    // ======================= FP32 SIMT fallback =======================
    __syncthreads();
    float* xs = (float*)base;            // [128][33]
    float* ws = (float*)base + 4224;     // [32][33]

    const int tx = tid & 7;
    const int ty = tid >> 3;
    const int wid0 = tid >> 5;
    const int wk  = tid & 31;

    const float* wptr[4];
    #pragma unroll
    for (int it = 0; it < 4; it++) {
        int c = it * 8 + wid0;
        wptr[it] = (c < 16) ? (l1_w + (size_t)(g * 16 + c) * KD)
                            : (l1f_w + (size_t)(c - 16) * KD);
    }
    const float* xptr[4];
    int xr_[4], xkv[4];
    #pragma unroll
    for (int it = 0; it < 4; it++) {
        int idx = it * 256 + tid;
        xr_[it] = idx >> 3;
        xkv[it] = idx & 7;
        xptr[it] = x + (size_t)sh_rows[xr_[it]] * KD + xkv[it] * 4;
    }

    float4 xreg[4];
    float  wreg[4];
    #pragma unroll
    for (int it = 0; it < 4; it++) {
        xreg[it] = *(const float4*)(xptr[it]);
        wreg[it] = wptr[it][wk];
    }

    float acc[4][4];
    #pragma unroll
    for (int i = 0; i < 4; i++)
        #pragma unroll
        for (int j = 0; j < 4; j++) acc[i][j] = 0.0f;

    const int NT = KD / 32;
    for (int kt = 0; kt < NT; kt++) {
        __syncthreads();
        #pragma unroll
        for (int it = 0; it < 4; it++) {
            int bofs = xr_[it] * 33 + xkv[it] * 4;
            xs[bofs + 0] = xreg[it].x;  xs[bofs + 1] = xreg[it].y;
            xs[bofs + 2] = xreg[it].z;  xs[bofs + 3] = xreg[it].w;
            ws[(it * 8 + wid0) * 33 + wk] = wreg[it];
        }
        __syncthreads();
        if (kt + 1 < NT) {
            int k0 = (kt + 1) * 32;
            #pragma unroll
            for (int it = 0; it < 4; it++) {
                xreg[it] = *(const float4*)(xptr[it] + k0);
                wreg[it] = wptr[it][k0 + wk];
            }
        }
        #pragma unroll
        for (int kk = 0; kk < 32; kk++) {
            float xv[4], wv[4];
            #pragma unroll
            for (int j = 0; j < 4; j++) {
                xv[j] = xs[(4 * ty + j) * 33 + kk];
                wv[j] = ws[(4 * tx + j) * 33 + kk];
            }
            #pragma unroll
            for (int i = 0; i < 4; i++)
                #pragma unroll
                for (int j = 0; j < 4; j++)
                    acc[i][j] = fmaf(xv[i], wv[j], acc[i][j]);
        }
    }
    __syncthreads();

    #pragma unroll
    for (int i = 0; i < 4; i++)
        #pragma unroll
        for (int j = 0; j < 4; j++)
            xs[(4 * ty + i) * 33 + (4 * tx + j)] = acc[i][j] + sh_bias[4 * tx + j];

    float* l1b   = xs;
    float* wsp   = (float*)base + 4224;
    float* sbs   = wsp + 5760;
    float* sgrid = sbs + 960;
    float* srden = sgrid + 300;
    kan_stage(tid, g, kan_grid, kan_coef, ksb, ksp, wsp, sbs, sgrid, srden);
    __syncthreads();

    kan_epilogue(tid, g, nrows, l1b, wsp, sbs, sgrid, srden,
                 sh_outw, sh_rows, out_b, out);
#endif
}

// ============================================================================
extern "C" void kernel_launch(void* const* d_in, const int* in_sizes, int n_in,
                              void* d_out, int out_size)
{
    const float* x        = (const float*)d_in[0];
    const int*   ls       = (const int*)  d_in[1];
    const float* l1_w     = (const float*)d_in[2];
    const float* l1_b     = (const float*)d_in[3];
    const float* l1f_w    = (const float*)d_in[4];
    const float* l1f_b    = (const float*)d_in[5];
    const float* kan_grid = (const float*)d_in[6];
    const float* kan_coef = (const float*)d_in[7];
    const float* ksb      = (const float*)d_in[8];
    const float* ksp      = (const float*)d_in[9];
    const float* out_w    = (const float*)d_in[10];
    const float* out_b    = (const float*)d_in[11];
    float* out = (float*)d_out;

    int B = in_sizes[1];

    cudaFuncSetAttribute(k_main, cudaFuncAttributeMaxDynamicSharedMemorySize,
                         ARENA_BYTES);

    int tiles = B / TB + NGRP;   // 136 <= 148 SMs: co-resident (grid barrier)
    k_main<<<tiles, 256, ARENA_BYTES>>>(x, ls, l1_w, l1_b, l1f_w, l1f_b,
                                        kan_grid, kan_coef, ksb, ksp,
                                        out_w, out_b, out, B);
}

// round 14
// speedup vs baseline: 1.7209x; 1.0055x over previous
#include <cuda_runtime.h>
#include <cuda_bf16.h>
#include <cstdint>

// Feature gate: tcgen05 ops exist only in the sm_103a/sm_100a passes.
#if defined(__CUDA_ARCH__) && (defined(__CUDA_ARCH_FEAT_SM103_ALL) || defined(__CUDA_ARCH_FEAT_SM100_ALL))
#define USE_TC 1
#else
#define USE_TC 0
#endif

#define B_MAX  16384
#define TB     128
#define KD     3072
#define NGRP   8
#define KTILE  64          // bf16 K elements per stage (128 B/row = SW128)
#define NST    48          // KD / KTILE
#define RING   3
#define STG    40960       // xhi 16K + xlo 16K + bhi 4K + blo 4K
#define IDESC  0x8080490u  // kind::f16, bf16 x bf16 -> f32, M=128, N=32

// -------- device scratch (zero-initialized at module load) --------
__device__ int g_counts[NGRP];
__device__ int g_cursor[NGRP];
__device__ int g_row_off[NGRP + 1];
__device__ int g_tile_off[NGRP + 1];
__device__ int g_perm[B_MAX];
__device__ unsigned g_barctr;          // monotonic grid-barrier counter
// pre-split, pre-swizzled weights: [g][ktile][hi 4096B | lo 4096B]
__device__ __align__(16) unsigned char g_bw[NGRP * NST * 8192];

// -------- PTX helpers --------
__device__ __forceinline__ unsigned su32(const void* p) {
    return (unsigned)__cvta_generic_to_shared(p);
}
__device__ __forceinline__ void mbar_init(unsigned a, unsigned cnt) {
    asm volatile("mbarrier.init.shared.b64 [%0], %1;" :: "r"(a), "r"(cnt) : "memory");
}
__device__ __forceinline__ void mbar_wait(unsigned a, unsigned ph) {
    asm volatile(
        "{\n\t.reg .pred P;\n\t"
        "W_%=:\n\t"
        "mbarrier.try_wait.parity.acquire.cta.shared::cta.b64 P, [%0], %1, 0x989680;\n\t"
        "@P bra.uni D_%=;\n\t"
        "bra.uni W_%=;\n\t"
        "D_%=:\n\t}"
        :: "r"(a), "r"(ph) : "memory");
}
__device__ __forceinline__ void fence_async() {
    asm volatile("fence.proxy.async.shared::cta;" ::: "memory");
}
__device__ __forceinline__ unsigned long long mk_desc(unsigned addr) {
    const unsigned long long BASE =
        (2ull << 61) | (1ull << 46) | (64ull << 32) | (1ull << 16); // SW128,SBO=64,LBO=1
    return BASE | ((unsigned long long)(addr >> 4) & 0x3FFF);
}
__device__ __forceinline__ void mma_f16_ss(unsigned d, unsigned long long ad,
                                           unsigned long long bd, bool en) {
#if USE_TC
    unsigned e = en ? 1u : 0u;
    asm volatile(
        "{\n\t.reg .pred p;\n\t"
        "setp.ne.u32 p, %4, 0;\n\t"
        "tcgen05.mma.cta_group::1.kind::f16 [%0], %1, %2, %3, {%5, %5, %5, %5}, p;\n\t"
        "}"
        :: "r"(d), "l"(ad), "l"(bd), "r"(IDESC), "r"(e), "r"(0u) : "memory");
#endif
}
__device__ __forceinline__ void tc_commit(unsigned bar) {
#if USE_TC
    asm volatile(
        "tcgen05.commit.cta_group::1.mbarrier::arrive::one.shared::cluster.b64 [%0];"
        :: "r"(bar) : "memory");
#endif
}

// Software grid barrier — valid because grid (<=136 CTAs, 1 CTA/SM via 171KB
// smem) is fully co-resident on 148 SMs. Monotonic counter: no reset needed
// across graph replays, and consecutive barriers can't alias.
__device__ __forceinline__ void grid_barrier(int tid) {
    __syncthreads();
    if (tid == 0) {
        __threadfence();
        unsigned G = gridDim.x;
        unsigned old = atomicAdd(&g_barctr, 1u);
        unsigned target = (old / G + 1u) * G;
        while (*(volatile unsigned*)&g_barctr < target) { }
        __threadfence();
    }
    __syncthreads();
}

// ============================================================================
// shared epilogue pieces
// ============================================================================
__device__ __forceinline__ void kan_stage(
    int tid, int g,
    const float* __restrict__ kan_grid, const float* __restrict__ kan_coef,
    const float* __restrict__ ksb,      const float* __restrict__ ksp,
    float* wsp, float* sbs, float* sgrid, float* srden)
{
    for (int t2 = tid; t2 < 5760; t2 += 256) {
        int k  = t2 % 6;
        int c  = (t2 / 6) & 31;
        int ii = t2 / 192;
        int id2 = ii * 256 + g * 32 + c;
        wsp[t2] = kan_coef[id2 * 6 + k] * ksp[id2];
    }
    for (int t2 = tid; t2 < 960; t2 += 256) {
        int c = t2 & 31, ii = t2 >> 5;
        sbs[t2] = ksb[ii * 256 + g * 32 + c];
    }
    for (int t2 = tid; t2 < 300; t2 += 256) sgrid[t2] = kan_grid[t2];
    for (int t2 = tid; t2 < 720; t2 += 256) {
        int ii = t2 / 24, j24 = t2 % 24;
        int d, j;
        if (j24 < 9)       { d = 1; j = j24; }
        else if (j24 < 17) { d = 2; j = j24 - 9; }
        else               { d = 3; j = j24 - 17; }
        const float* gr = kan_grid + ii * 10;
        srden[t2] = 1.0f / (gr[j + d] - gr[j]);
    }
}

__device__ __forceinline__ void kan_epilogue(
    int tid, int g, int nrows,
    const float* l1b, const float* wsp, const float* sbs,
    const float* sgrid, const float* srden, const float* sh_outw,
    const int* sh_rows, const float* __restrict__ out_b, float* __restrict__ out)
{
    const int r = tid >> 1, h = tid & 1;
    const float* lrow = l1b + r * 33;
    const float l1c_out = lrow[15];
    const float l1f_out = lrow[31];

    float a[30];
    #pragma unroll
    for (int i = 0; i < 15; i++) {
        float z = lrow[i] + lrow[16 + i];
        float q = (z * z) * (127.0f / 128.0f);
        a[i]      = fminf(fmaxf(q, 0.0f), 1.0f);
        a[i + 15] = fminf(fmaxf(z, 0.0f), 1.0f);
    }

    float acc2[16];
    #pragma unroll
    for (int c = 0; c < 16; c++) acc2[c] = 0.0f;

    #pragma unroll
    for (int i = 0; i < 30; i++) {
        const float* gr = sgrid + i * 10;
        const float* rd = srden + i * 24;
        const float xv  = a[i];

        float b[9];
        #pragma unroll
        for (int j = 0; j < 9; j++)
            b[j] = (xv >= gr[j] && xv < gr[j + 1]) ? 1.0f : 0.0f;
        #pragma unroll
        for (int d = 1; d <= 3; d++) {
            const float* rdd = rd + (d == 1 ? 0 : (d == 2 ? 9 : 17));
            #pragma unroll
            for (int j = 0; j <= 8 - d; j++)
                b[j] = (xv - gr[j]) * rdd[j] * b[j]
                     + (gr[j + d + 1] - xv) * rdd[j + 1] * b[j + 1];
        }
        const float sv = xv / (1.0f + __expf(-xv));

        const float* sbp = sbs + i * 32 + h * 16;
        const float* wp  = wsp + (i * 32 + h * 16) * 6;
        #pragma unroll
        for (int c = 0; c < 16; c++) {
            float tt = sv * sbp[c];
            #pragma unroll
            for (int k = 0; k < 6; k++)
                tt = fmaf(b[k], wp[c * 6 + k], tt);
            acc2[c] += tt;
        }
    }

    float part = 0.0f;
    #pragma unroll
    for (int c = 0; c < 16; c++) {
        float v = fminf(fmaxf(acc2[c], 0.0f), 1.0f);
        part = fmaf(v, sh_outw[h * 16 + c], part);
    }
    part += __shfl_xor_sync(0xffffffffu, part, 1);

    if (h == 0 && r < nrows)
        out[sh_rows[r]] = part + out_b[g] + l1f_out + l1c_out;
}

// ============================================================================
// single fused kernel: sort + weight prep (phase 1, grid barriers) + tile body
// ============================================================================
#define ARENA_BYTES (RING * STG + 47856 + 1024)

__global__ void __launch_bounds__(256, 1) k_main(
    const float* __restrict__ x,        const int* __restrict__ ls,
    const float* __restrict__ l1_w,     const float* __restrict__ l1_b,
    const float* __restrict__ l1f_w,    const float* __restrict__ l1f_b,
    const float* __restrict__ kan_grid, const float* __restrict__ kan_coef,
    const float* __restrict__ ksb,      const float* __restrict__ ksp,
    const float* __restrict__ out_w,    const float* __restrict__ out_b,
    float* __restrict__ out,            int B)
{
    extern __shared__ char raw[];
    __shared__ __align__(8) unsigned long long sh_empty[RING];
    __shared__ unsigned sh_tmem[1];
    __shared__ int   sh_rows[TB];
    __shared__ float sh_bias[32];
    __shared__ float sh_outw[32];

    const int bid = blockIdx.x, tid = threadIdx.x;
    const int gidx = bid * 256 + tid;
    const int nthr = (int)gridDim.x * 256;
    const int lane = tid & 31;

    // ================= phase 1: weight split + histogram =================
    for (int idx = gidx; idx < NGRP * NST * 32 * 32; idx += nthr) {
        int kp  = idx & 31;
        int row = (idx >> 5) & 31;
        int kt  = (idx >> 10) % NST;
        int g   = (idx >> 10) / NST;
        int gk  = kt * KTILE + kp * 2;
        const float* src = (row < 16) ? (l1_w + (size_t)(g * 16 + row) * KD + gk)
                                      : (l1f_w + (size_t)(row - 16) * KD + gk);
        float w0 = src[0], w1 = src[1];
        __nv_bfloat162 h = __floats2bfloat162_rn(w0, w1);
        float2 hf = __bfloat1622float2(h);
        __nv_bfloat162 l = __floats2bfloat162_rn(w0 - hf.x, w1 - hf.y);
        unsigned off = row * 128 + kp * 4;
        off ^= (off >> 3) & 0x70;                       // SW128
        unsigned char* bp = g_bw + (size_t)(g * NST + kt) * 8192;
        *(__nv_bfloat162*)(bp + off)        = h;
        *(__nv_bfloat162*)(bp + 4096 + off) = l;
    }
    int my_g = -1;
    if (gidx < B) {                     // B is a multiple of 32: warps uniform
        my_g = ls[gidx];
        unsigned m = __match_any_sync(0xffffffffu, my_g);
        if ((int)(__ffs(m) - 1) == lane) atomicAdd(&g_counts[my_g], __popc(m));
    }
    grid_barrier(tid);

    // prefix (block 0), then re-zero counts for the next graph replay
    if (bid == 0 && tid == 0) {
        int s = 0, t = 0;
        for (int g = 0; g < NGRP; g++) {
            g_row_off[g] = s;  g_tile_off[g] = t;  g_cursor[g] = s;
            s += g_counts[g];
            t += (g_counts[g] + TB - 1) / TB;
            g_counts[g] = 0;
        }
        g_row_off[NGRP] = s;  g_tile_off[NGRP] = t;
    }
    grid_barrier(tid);

    // scatter
    if (gidx < B) {
        unsigned m = __match_any_sync(0xffffffffu, my_g);
        int leader = __ffs(m) - 1;
        int rank = __popc(m & ((1u << lane) - 1u));
        int base0 = 0;
        if (lane == leader) base0 = atomicAdd(&g_cursor[my_g], __popc(m));
        base0 = __shfl_sync(0xffffffffu, base0, leader);
        g_perm[base0 + rank] = gidx;
    }
    grid_barrier(tid);

    // ================= phase 2: tile body =================
    int g = 0;
    #pragma unroll
    for (int i = 0; i < NGRP; i++)
        if (bid >= g_tile_off[i + 1]) g = i + 1;
    if (g >= NGRP) return;   // whole block exits (all barriers already passed)

    const int tile_in_g = bid - g_tile_off[g];
    const int row_start = g_row_off[g] + tile_in_g * TB;
    int nrows = g_row_off[g + 1] - row_start;
    if (nrows > TB) nrows = TB;

    if (tid < TB) {
        int rr = tid < nrows ? tid : (nrows - 1);
        sh_rows[tid] = g_perm[row_start + rr];
    }
    if (tid < 16)       sh_bias[tid] = l1_b[g * 16 + tid];
    else if (tid < 32)  sh_bias[tid] = l1f_b[tid - 16];
    if (tid < 32)       sh_outw[tid] = out_w[g * 32 + tid];

    char* base = (char*)(((uintptr_t)raw + 1023) & ~(uintptr_t)1023);

#if USE_TC
    // ======================= tensor-core path =======================
    if (tid == 0) {
        #pragma unroll
        for (int s = 0; s < RING; s++)
            mbar_init(su32(&sh_empty[s]), 1);
    }
    if (tid < 32) {
        asm volatile("tcgen05.alloc.cta_group::1.sync.aligned.shared::cta.b32 [%0], 64;"
                     :: "r"(su32(sh_tmem)) : "memory");
        asm volatile("tcgen05.relinquish_alloc_permit.cta_group::1.sync.aligned;");
    }
    __syncthreads();
    const unsigned tmem = sh_tmem[0];

    char* stg[RING];
    unsigned long long dxh[RING], dxl[RING], dbh[RING], dbl[RING];
    #pragma unroll
    for (int s = 0; s < RING; s++) {
        stg[s] = base + s * STG;
        dxh[s] = mk_desc(su32(stg[s]));
        dxl[s] = mk_desc(su32(stg[s] + 16384));
        dbh[s] = mk_desc(su32(stg[s] + 32768));
        dbl[s] = mk_desc(su32(stg[s] + 36864));
    }

    // coalesced producer mapping: warp covers 2 rows x 256B -> 4 wavefronts
    const int sub  = tid >> 4;
    const float* rptr[8];
    unsigned swoff[8];
    #pragma unroll
    for (int i = 0; i < 8; i++) {
        int row = i * 16 + sub;
        rptr[i] = x + (size_t)sh_rows[row] * KD + (tid & 15) * 4;
        unsigned off = (unsigned)(row * 128 + (tid & 15) * 8);
        swoff[i] = off ^ ((off >> 3) & 0x70);
    }
    const unsigned char* bsrc = g_bw + (size_t)g * NST * 8192 + (size_t)tid * 16;

    float4 xf[8];
    uint4 bvh, bvl;
    #pragma unroll
    for (int i = 0; i < 8; i++) xf[i] = *(const float4*)(rptr[i]);
    bvh = *(const uint4*)(bsrc);
    bvl = *(const uint4*)(bsrc + 4096);

    int s = 0, pph = 1;
    bool en = false;

    for (int t = 0; t < NST; t++) {
        mbar_wait(su32(&sh_empty[s]), (unsigned)pph);

        char* xh = stg[s];
        char* xl = stg[s] + 16384;
        #pragma unroll
        for (int i = 0; i < 8; i++) {
            float4 f = xf[i];
            // cheap truncation split: hi = top 16 bits (exact bf16),
            // lo = f - hi (exact FADD), only lo-pack needs CVT.
            unsigned a0 = __float_as_uint(f.x), a1 = __float_as_uint(f.y);
            unsigned a2 = __float_as_uint(f.z), a3 = __float_as_uint(f.w);
            unsigned h01 = __byte_perm(a0, a1, 0x7632);
            unsigned h23 = __byte_perm(a2, a3, 0x7632);
            float l0 = f.x - __uint_as_float(a0 & 0xffff0000u);
            float l1 = f.y - __uint_as_float(a1 & 0xffff0000u);
            float l2 = f.z - __uint_as_float(a2 & 0xffff0000u);
            float l3 = f.w - __uint_as_float(a3 & 0xffff0000u);
            __nv_bfloat162 lo01 = __floats2bfloat162_rn(l0, l1);
            __nv_bfloat162 lo23 = __floats2bfloat162_rn(l2, l3);
            *(uint2*)(xh + swoff[i]) = make_uint2(h01, h23);
            *(uint2*)(xl + swoff[i]) =
                make_uint2(*(unsigned*)&lo01, *(unsigned*)&lo23);
        }
        *(uint4*)(stg[s] + 32768 + tid * 16) = bvh;
        *(uint4*)(stg[s] + 36864 + tid * 16) = bvl;

        // prefetch next stage NOW (xf last used above) — maximizes LDG cover
        if (t + 1 < NST) {
            int k0 = (t + 1) * KTILE;
            #pragma unroll
            for (int i = 0; i < 8; i++) xf[i] = *(const float4*)(rptr[i] + k0);
            bvh = *(const uint4*)(bsrc + (size_t)(t + 1) * 8192);
            bvl = *(const uint4*)(bsrc + (size_t)(t + 1) * 8192 + 4096);
        }

        fence_async();
        __syncthreads();                  // stage s image complete

        if (tid == 0) {
            #pragma unroll
            for (int ks = 0; ks < 4; ks++) {
                unsigned long long o = (unsigned long long)(ks * 2);
                mma_f16_ss(tmem, dxh[s] + o, dbh[s] + o, en); en = true;
                mma_f16_ss(tmem, dxh[s] + o, dbl[s] + o, true);
                mma_f16_ss(tmem, dxl[s] + o, dbh[s] + o, true);
            }
            tc_commit(su32(&sh_empty[s]));
        }

        if (++s == RING) { s = 0; pph ^= 1; }
    }

    // stage KAN params while the tail MMAs drain
    float* l1b   = (float*)(base + RING * STG);
    float* wsp   = l1b + 4224;
    float* sbs   = wsp + 5760;
    float* sgrid = sbs + 960;
    float* srden = sgrid + 300;
    kan_stage(tid, g, kan_grid, kan_coef, ksb, ksp, wsp, sbs, sgrid, srden);

    // wait for the LAST stage's MMA group (same-accumulator MMAs complete in
    // order, so its commit implies all MMAs done).
    mbar_wait(su32(&sh_empty[(NST - 1) % RING]), (unsigned)pph);
    asm volatile("tcgen05.fence::after_thread_sync;" ::: "memory");

    const int wid = tid >> 5, lid = tid & 31;
    if (wid < 4) {
        unsigned dr[32];
        asm volatile(
            "tcgen05.ld.sync.aligned.32x32b.x32.b32 "
            "{%0,%1,%2,%3,%4,%5,%6,%7,%8,%9,%10,%11,%12,%13,%14,%15,"
            "%16,%17,%18,%19,%20,%21,%22,%23,%24,%25,%26,%27,%28,%29,%30,%31}, [%32];"
            : "=r"(dr[0]), "=r"(dr[1]), "=r"(dr[2]), "=r"(dr[3]),
              "=r"(dr[4]), "=r"(dr[5]), "=r"(dr[6]), "=r"(dr[7]),
              "=r"(dr[8]), "=r"(dr[9]), "=r"(dr[10]), "=r"(dr[11]),
              "=r"(dr[12]), "=r"(dr[13]), "=r"(dr[14]), "=r"(dr[15]),
              "=r"(dr[16]), "=r"(dr[17]), "=r"(dr[18]), "=r"(dr[19]),
              "=r"(dr[20]), "=r"(dr[21]), "=r"(dr[22]), "=r"(dr[23]),
              "=r"(dr[24]), "=r"(dr[25]), "=r"(dr[26]), "=r"(dr[27]),
              "=r"(dr[28]), "=r"(dr[29]), "=r"(dr[30]), "=r"(dr[31])
            : "r"(tmem));
        asm volatile("tcgen05.wait::ld.sync.aligned;" ::: "memory");
        int row = wid * 32 + lid;
        #pragma unroll
        for (int c = 0; c < 32; c++)
            l1b[row * 33 + c] = __uint_as_float(dr[c]) + sh_bias[c];
        asm volatile("tcgen05.fence::before_thread_sync;" ::: "memory");
    }
    __syncthreads();

    kan_epilogue(tid, g, nrows, l1b, wsp, sbs, sgrid, srden,
                 sh_outw, sh_rows, out_b, out);

    __syncthreads();
    if (tid < 32) {
        asm volatile("tcgen05.dealloc.cta_group::1.sync.aligned.b32 %0, 64;"
                     :: "r"(tmem));
    }

#else
    // ======================= FP32 SIMT fallback =======================
    __syncthreads();
    float* xs = (float*)base;            // [128][33]
    float* ws = (float*)base + 4224;     // [32][33]

    const int tx = tid & 7;
    const int ty = tid >> 3;
    const int wid0 = tid >> 5;
    const int wk  = tid & 31;

    const float* wptr[4];
    #pragma unroll
    for (int it = 0; it < 4; it++) {
        int c = it * 8 + wid0;
        wptr[it] = (c < 16) ? (l1_w + (size_t)(g * 16 + c) * KD)
                            : (l1f_w + (size_t)(c - 16) * KD);
    }
    const float* xptr[4];
    int xr_[4], xkv[4];
    #pragma unroll
    for (int it = 0; it < 4; it++) {
        int idx = it * 256 + tid;
        xr_[it] = idx >> 3;
        xkv[it] = idx & 7;
        xptr[it] = x + (size_t)sh_rows[xr_[it]] * KD + xkv[it] * 4;
    }

    float4 xreg[4];
    float  wreg[4];
    #pragma unroll
    for (int it = 0; it < 4; it++) {
        xreg[it] = *(const float4*)(xptr[it]);
        wreg[it] = wptr[it][wk];
    }

    float acc[4][4];
    #pragma unroll
    for (int i = 0; i < 4; i++)
        #pragma unroll
        for (int j = 0; j < 4; j++) acc[i][j] = 0.0f;

    const int NT = KD / 32;
    for (int kt = 0; kt < NT; kt++) {
        __syncthreads();
        #pragma unroll
        for (int it = 0; it < 4; it++) {
            int bofs = xr_[it] * 33 + xkv[it] * 4;
            xs[bofs + 0] = xreg[it].x;  xs[bofs + 1] = xreg[it].y;
            xs[bofs + 2] = xreg[it].z;  xs[bofs + 3] = xreg[it].w;
            ws[(it * 8 + wid0) * 33 + wk] = wreg[it];
        }
        __syncthreads();
        if (kt + 1 < NT) {
            int k0 = (kt + 1) * 32;
            #pragma unroll
            for (int it = 0; it < 4; it++) {
                xreg[it] = *(const float4*)(xptr[it] + k0);
                wreg[it] = wptr[it][k0 + wk];
            }
        }
        #pragma unroll
        for (int kk = 0; kk < 32; kk++) {
            float xv[4], wv[4];
            #pragma unroll
            for (int j = 0; j < 4; j++) {
                xv[j] = xs[(4 * ty + j) * 33 + kk];
                wv[j] = ws[(4 * tx + j) * 33 + kk];
            }
            #pragma unroll
            for (int i = 0; i < 4; i++)
                #pragma unroll
                for (int j = 0; j < 4; j++)
                    acc[i][j] = fmaf(xv[i], wv[j], acc[i][j]);
        }
    }
    __syncthreads();

    #pragma unroll
    for (int i = 0; i < 4; i++)
        #pragma unroll
        for (int j = 0; j < 4; j++)
            xs[(4 * ty + i) * 33 + (4 * tx + j)] = acc[i][j] + sh_bias[4 * tx + j];

    float* l1b   = xs;
    float* wsp   = (float*)base + 4224;
    float* sbs   = wsp + 5760;
    float* sgrid = sbs + 960;
    float* srden = sgrid + 300;
    kan_stage(tid, g, kan_grid, kan_coef, ksb, ksp, wsp, sbs, sgrid, srden);
    __syncthreads();

    kan_epilogue(tid, g, nrows, l1b, wsp, sbs, sgrid, srden,
                 sh_outw, sh_rows, out_b, out);
#endif
}

// ============================================================================
extern "C" void kernel_launch(void* const* d_in, const int* in_sizes, int n_in,
                              void* d_out, int out_size)
{
    const float* x        = (const float*)d_in[0];
    const int*   ls       = (const int*)  d_in[1];
    const float* l1_w     = (const float*)d_in[2];
    const float* l1_b     = (const float*)d_in[3];
    const float* l1f_w    = (const float*)d_in[4];
    const float* l1f_b    = (const float*)d_in[5];
    const float* kan_grid = (const float*)d_in[6];
    const float* kan_coef = (const float*)d_in[7];
    const float* ksb      = (const float*)d_in[8];
    const float* ksp      = (const float*)d_in[9];
    const float* out_w    = (const float*)d_in[10];
    const float* out_b    = (const float*)d_in[11];
    float* out = (float*)d_out;

    int B = in_sizes[1];

    cudaFuncSetAttribute(k_main, cudaFuncAttributeMaxDynamicSharedMemorySize,
                         ARENA_BYTES);

    int tiles = B / TB + NGRP;   // 136 <= 148 SMs: co-resident (grid barrier)
    k_main<<<tiles, 256, ARENA_BYTES>>>(x, ls, l1_w, l1_b, l1f_w, l1f_b,
                                        kan_grid, kan_coef, ksb, ksp,
                                        out_w, out_b, out, B);
}

// round 15
// speedup vs baseline: 1.8754x; 1.0898x over previous
#include <cuda_runtime.h>
#include <cuda_bf16.h>
#include <cstdint>

// Feature gate: tcgen05 ops exist only in the sm_103a/sm_100a passes.
#if defined(__CUDA_ARCH__) && (defined(__CUDA_ARCH_FEAT_SM103_ALL) || defined(__CUDA_ARCH_FEAT_SM100_ALL))
#define USE_TC 1
#else
#define USE_TC 0
#endif

#define B_MAX  16384
#define TB     128
#define KD     3072
#define NGRP   8
#define KTILE  64          // bf16 K elements per stage (128 B/row = SW128)
#define NST    48          // KD / KTILE
#define RING   3
#define STG    40960       // xhi 16K + xlo 16K + bhi 4K + blo 4K
#define THREADS 288        // warp 0 = MMA issuer, warps 1..8 = producers
#define IDESC  0x8080490u  // kind::f16, bf16 x bf16 -> f32, M=128, N=32

// -------- device scratch (zero-initialized at module load) --------
__device__ int g_counts[NGRP];
__device__ int g_cursor[NGRP];
__device__ int g_row_off[NGRP + 1];
__device__ int g_tile_off[NGRP + 1];
__device__ int g_perm[B_MAX];
__device__ unsigned g_barctr;          // monotonic grid-barrier counter
// pre-split, pre-swizzled weights: [g][ktile][hi 4096B | lo 4096B]
__device__ __align__(16) unsigned char g_bw[NGRP * NST * 8192];

// -------- PTX helpers --------
__device__ __forceinline__ unsigned su32(const void* p) {
    return (unsigned)__cvta_generic_to_shared(p);
}
__device__ __forceinline__ void mbar_init(unsigned a, unsigned cnt) {
    asm volatile("mbarrier.init.shared.b64 [%0], %1;" :: "r"(a), "r"(cnt) : "memory");
}
__device__ __forceinline__ void mbar_arrive(unsigned a) {
    asm volatile("mbarrier.arrive.release.cta.shared::cta.b64 _, [%0];"
                 :: "r"(a) : "memory");
}
__device__ __forceinline__ void mbar_wait(unsigned a, unsigned ph) {
    asm volatile(
        "{\n\t.reg .pred P;\n\t"
        "W_%=:\n\t"
        "mbarrier.try_wait.parity.acquire.cta.shared::cta.b64 P, [%0], %1, 0x989680;\n\t"
        "@P bra.uni D_%=;\n\t"
        "bra.uni W_%=;\n\t"
        "D_%=:\n\t}"
        :: "r"(a), "r"(ph) : "memory");
}
__device__ __forceinline__ void fence_async() {
    asm volatile("fence.proxy.async.shared::cta;" ::: "memory");
}
__device__ __forceinline__ unsigned long long mk_desc(unsigned addr) {
    const unsigned long long BASE =
        (2ull << 61) | (1ull << 46) | (64ull << 32) | (1ull << 16); // SW128,SBO=64,LBO=1
    return BASE | ((unsigned long long)(addr >> 4) & 0x3FFF);
}
__device__ __forceinline__ void mma_f16_ss(unsigned d, unsigned long long ad,
                                           unsigned long long bd, bool en) {
#if USE_TC
    unsigned e = en ? 1u : 0u;
    asm volatile(
        "{\n\t.reg .pred p;\n\t"
        "setp.ne.u32 p, %4, 0;\n\t"
        "tcgen05.mma.cta_group::1.kind::f16 [%0], %1, %2, %3, {%5, %5, %5, %5}, p;\n\t"
        "}"
        :: "r"(d), "l"(ad), "l"(bd), "r"(IDESC), "r"(e), "r"(0u) : "memory");
#endif
}
__device__ __forceinline__ void tc_commit(unsigned bar) {
#if USE_TC
    asm volatile(
        "tcgen05.commit.cta_group::1.mbarrier::arrive::one.shared::cluster.b64 [%0];"
        :: "r"(bar) : "memory");
#endif
}

// Software grid barrier — valid because the grid (<=136 CTAs, 1 CTA/SM) is
// fully co-resident on 148 SMs. Monotonic counter: no reset across replays.
__device__ __forceinline__ void grid_barrier(int tid) {
    __syncthreads();
    if (tid == 0) {
        __threadfence();
        unsigned G = gridDim.x;
        unsigned old = atomicAdd(&g_barctr, 1u);
        unsigned target = (old / G + 1u) * G;
        while (*(volatile unsigned*)&g_barctr < target) { }
        __threadfence();
    }
    __syncthreads();
}

// ============================================================================
// shared epilogue pieces
// ============================================================================
__device__ __forceinline__ void kan_stage(
    int tid, int g,
    const float* __restrict__ kan_grid, const float* __restrict__ kan_coef,
    const float* __restrict__ ksb,      const float* __restrict__ ksp,
    float* wsp, float* sbs, float* sgrid, float* srden)
{
    for (int t2 = tid; t2 < 5760; t2 += THREADS) {
        int k  = t2 % 6;
        int c  = (t2 / 6) & 31;
        int ii = t2 / 192;
        int id2 = ii * 256 + g * 32 + c;
        wsp[t2] = kan_coef[id2 * 6 + k] * ksp[id2];
    }
    for (int t2 = tid; t2 < 960; t2 += THREADS) {
        int c = t2 & 31, ii = t2 >> 5;
        sbs[t2] = ksb[ii * 256 + g * 32 + c];
    }
    for (int t2 = tid; t2 < 300; t2 += THREADS) sgrid[t2] = kan_grid[t2];
    for (int t2 = tid; t2 < 720; t2 += THREADS) {
        int ii = t2 / 24, j24 = t2 % 24;
        int d, j;
        if (j24 < 9)       { d = 1; j = j24; }
        else if (j24 < 17) { d = 2; j = j24 - 9; }
        else               { d = 3; j = j24 - 17; }
        const float* gr = kan_grid + ii * 10;
        srden[t2] = 1.0f / (gr[j + d] - gr[j]);
    }
}

__device__ __forceinline__ void kan_epilogue(
    int tid, int g, int nrows,
    const float* l1b, const float* wsp, const float* sbs,
    const float* sgrid, const float* srden, const float* sh_outw,
    const int* sh_rows, const float* __restrict__ out_b, float* __restrict__ out)
{
    const int r = tid >> 1, h = tid & 1;
    const float* lrow = l1b + r * 33;
    const float l1c_out = lrow[15];
    const float l1f_out = lrow[31];

    float a[30];
    #pragma unroll
    for (int i = 0; i < 15; i++) {
        float z = lrow[i] + lrow[16 + i];
        float q = (z * z) * (127.0f / 128.0f);
        a[i]      = fminf(fmaxf(q, 0.0f), 1.0f);
        a[i + 15] = fminf(fmaxf(z, 0.0f), 1.0f);
    }

    float acc2[16];
    #pragma unroll
    for (int c = 0; c < 16; c++) acc2[c] = 0.0f;

    #pragma unroll
    for (int i = 0; i < 30; i++) {
        const float* gr = sgrid + i * 10;
        const float* rd = srden + i * 24;
        const float xv  = a[i];

        float b[9];
        #pragma unroll
        for (int j = 0; j < 9; j++)
            b[j] = (xv >= gr[j] && xv < gr[j + 1]) ? 1.0f : 0.0f;
        #pragma unroll
        for (int d = 1; d <= 3; d++) {
            const float* rdd = rd + (d == 1 ? 0 : (d == 2 ? 9 : 17));
            #pragma unroll
            for (int j = 0; j <= 8 - d; j++)
                b[j] = (xv - gr[j]) * rdd[j] * b[j]
                     + (gr[j + d + 1] - xv) * rdd[j + 1] * b[j + 1];
        }
        const float sv = xv / (1.0f + __expf(-xv));

        const float* sbp = sbs + i * 32 + h * 16;
        const float* wp  = wsp + (i * 32 + h * 16) * 6;
        #pragma unroll
        for (int c = 0; c < 16; c++) {
            float tt = sv * sbp[c];
            #pragma unroll
            for (int k = 0; k < 6; k++)
                tt = fmaf(b[k], wp[c * 6 + k], tt);
            acc2[c] += tt;
        }
    }

    float part = 0.0f;
    #pragma unroll
    for (int c = 0; c < 16; c++) {
        float v = fminf(fmaxf(acc2[c], 0.0f), 1.0f);
        part = fmaf(v, sh_outw[h * 16 + c], part);
    }
    part += __shfl_xor_sync(0xffffffffu, part, 1);

    if (h == 0 && r < nrows)
        out[sh_rows[r]] = part + out_b[g] + l1f_out + l1c_out;
}

// ============================================================================
// single fused kernel: sort + weight prep (phase 1) + warp-specialized body
// ============================================================================
#define ARENA_BYTES (RING * STG + 47856 + 1024)

__global__ void __launch_bounds__(THREADS, 1) k_main(
    const float* __restrict__ x,        const int* __restrict__ ls,
    const float* __restrict__ l1_w,     const float* __restrict__ l1_b,
    const float* __restrict__ l1f_w,    const float* __restrict__ l1f_b,
    const float* __restrict__ kan_grid, const float* __restrict__ kan_coef,
    const float* __restrict__ ksb,      const float* __restrict__ ksp,
    const float* __restrict__ out_w,    const float* __restrict__ out_b,
    float* __restrict__ out,            int B)
{
    extern __shared__ char raw[];
    __shared__ __align__(8) unsigned long long sh_empty[RING], sh_full[RING];
    __shared__ unsigned sh_tmem[1];
    __shared__ int   sh_rows[TB];
    __shared__ float sh_bias[32];
    __shared__ float sh_outw[32];

    const int bid = blockIdx.x, tid = threadIdx.x;
    const int gidx = bid * THREADS + tid;
    const int nthr = (int)gridDim.x * THREADS;
    const int lane = tid & 31;

    // ================= phase 1: weight split + histogram =================
    for (int idx = gidx; idx < NGRP * NST * 32 * 32; idx += nthr) {
        int kp  = idx & 31;
        int row = (idx >> 5) & 31;
        int kt  = (idx >> 10) % NST;
        int g   = (idx >> 10) / NST;
        int gk  = kt * KTILE + kp * 2;
        const float* src = (row < 16) ? (l1_w + (size_t)(g * 16 + row) * KD + gk)
                                      : (l1f_w + (size_t)(row - 16) * KD + gk);
        float w0 = src[0], w1 = src[1];
        __nv_bfloat162 h = __floats2bfloat162_rn(w0, w1);
        float2 hf = __bfloat1622float2(h);
        __nv_bfloat162 l = __floats2bfloat162_rn(w0 - hf.x, w1 - hf.y);
        unsigned off = row * 128 + kp * 4;
        off ^= (off >> 3) & 0x70;                       // SW128
        unsigned char* bp = g_bw + (size_t)(g * NST + kt) * 8192;
        *(__nv_bfloat162*)(bp + off)        = h;
        *(__nv_bfloat162*)(bp + 4096 + off) = l;
    }
    int my_g = -1;
    if (gidx < B) {                     // warp-uniform: B and bases are %32==0
        my_g = ls[gidx];
        unsigned m = __match_any_sync(0xffffffffu, my_g);
        if ((int)(__ffs(m) - 1) == lane) atomicAdd(&g_counts[my_g], __popc(m));
    }
    grid_barrier(tid);

    if (bid == 0 && tid == 0) {
        int s = 0, t = 0;
        for (int g = 0; g < NGRP; g++) {
            g_row_off[g] = s;  g_tile_off[g] = t;  g_cursor[g] = s;
            s += g_counts[g];
            t += (g_counts[g] + TB - 1) / TB;
            g_counts[g] = 0;
        }
        g_row_off[NGRP] = s;  g_tile_off[NGRP] = t;
    }
    grid_barrier(tid);

    if (gidx < B) {
        unsigned m = __match_any_sync(0xffffffffu, my_g);
        int leader = __ffs(m) - 1;
        int rank = __popc(m & ((1u << lane) - 1u));
        int base0 = 0;
        if (lane == leader) base0 = atomicAdd(&g_cursor[my_g], __popc(m));
        base0 = __shfl_sync(0xffffffffu, base0, leader);
        g_perm[base0 + rank] = gidx;
    }
    grid_barrier(tid);

    // ================= phase 2: tile body =================
    int g = 0;
    #pragma unroll
    for (int i = 0; i < NGRP; i++)
        if (bid >= g_tile_off[i + 1]) g = i + 1;
    if (g >= NGRP) return;

    const int tile_in_g = bid - g_tile_off[g];
    const int row_start = g_row_off[g] + tile_in_g * TB;
    int nrows = g_row_off[g + 1] - row_start;
    if (nrows > TB) nrows = TB;

    if (tid < TB) {
        int rr = tid < nrows ? tid : (nrows - 1);
        sh_rows[tid] = g_perm[row_start + rr];
    }
    if (tid < 16)       sh_bias[tid] = l1_b[g * 16 + tid];
    else if (tid < 32)  sh_bias[tid] = l1f_b[tid - 16];
    if (tid < 32)       sh_outw[tid] = out_w[g * 32 + tid];

    char* base = (char*)(((uintptr_t)raw + 1023) & ~(uintptr_t)1023);

#if USE_TC
    // ======================= tensor-core path =======================
    if (tid == 0) {
        #pragma unroll
        for (int s = 0; s < RING; s++) {
            mbar_init(su32(&sh_empty[s]), 1);
            mbar_init(su32(&sh_full[s]), 256);   // 8 producer warps x 32
        }
    }
    if (tid < 32) {
        asm volatile("tcgen05.alloc.cta_group::1.sync.aligned.shared::cta.b32 [%0], 64;"
                     :: "r"(su32(sh_tmem)) : "memory");
        asm volatile("tcgen05.relinquish_alloc_permit.cta_group::1.sync.aligned;");
    }
    __syncthreads();
    const unsigned tmem = sh_tmem[0];

    char* stg[RING];
    unsigned long long dxh[RING], dxl[RING], dbh[RING], dbl[RING];
    #pragma unroll
    for (int s = 0; s < RING; s++) {
        stg[s] = base + s * STG;
        dxh[s] = mk_desc(su32(stg[s]));
        dxl[s] = mk_desc(su32(stg[s] + 16384));
        dbh[s] = mk_desc(su32(stg[s] + 32768));
        dbl[s] = mk_desc(su32(stg[s] + 36864));
    }

    const int wid = tid >> 5;

    if (wid >= 1) {
        // -------------------- producer warps 1..8 --------------------
        const int ptid = tid - 32;          // 0..255
        const int sub  = ptid >> 4;
        const float* rptr[8];
        unsigned swoff[8];
        #pragma unroll
        for (int i = 0; i < 8; i++) {
            int row = i * 16 + sub;
            rptr[i] = x + (size_t)sh_rows[row] * KD + (ptid & 15) * 4;
            unsigned off = (unsigned)(row * 128 + (ptid & 15) * 8);
            swoff[i] = off ^ ((off >> 3) & 0x70);
        }
        const unsigned char* bsrc = g_bw + (size_t)g * NST * 8192 + (size_t)ptid * 16;

        float4 xf[8];
        uint4 bvh, bvl;
        #pragma unroll
        for (int i = 0; i < 8; i++) xf[i] = *(const float4*)(rptr[i]);
        bvh = *(const uint4*)(bsrc);
        bvl = *(const uint4*)(bsrc + 4096);

        int s = 0, pph = 1;
        for (int t = 0; t < NST; t++) {
            mbar_wait(su32(&sh_empty[s]), (unsigned)pph);

            char* xh = stg[s];
            char* xl = stg[s] + 16384;
            #pragma unroll
            for (int i = 0; i < 8; i++) {
                float4 f = xf[i];
                unsigned a0 = __float_as_uint(f.x), a1 = __float_as_uint(f.y);
                unsigned a2 = __float_as_uint(f.z), a3 = __float_as_uint(f.w);
                unsigned h01 = __byte_perm(a0, a1, 0x7632);
                unsigned h23 = __byte_perm(a2, a3, 0x7632);
                float l0 = f.x - __uint_as_float(a0 & 0xffff0000u);
                float l1 = f.y - __uint_as_float(a1 & 0xffff0000u);
                float l2 = f.z - __uint_as_float(a2 & 0xffff0000u);
                float l3 = f.w - __uint_as_float(a3 & 0xffff0000u);
                __nv_bfloat162 lo01 = __floats2bfloat162_rn(l0, l1);
                __nv_bfloat162 lo23 = __floats2bfloat162_rn(l2, l3);
                *(uint2*)(xh + swoff[i]) = make_uint2(h01, h23);
                *(uint2*)(xl + swoff[i]) =
                    make_uint2(*(unsigned*)&lo01, *(unsigned*)&lo23);
            }
            *(uint4*)(stg[s] + 32768 + ptid * 16) = bvh;
            *(uint4*)(stg[s] + 36864 + ptid * 16) = bvl;

            if (t + 1 < NST) {              // prefetch next stage
                int k0 = (t + 1) * KTILE;
                #pragma unroll
                for (int i = 0; i < 8; i++) xf[i] = *(const float4*)(rptr[i] + k0);
                bvh = *(const uint4*)(bsrc + (size_t)(t + 1) * 8192);
                bvl = *(const uint4*)(bsrc + (size_t)(t + 1) * 8192 + 4096);
            }

            fence_async();
            mbar_arrive(su32(&sh_full[s]));  // slice done; run ahead freely

            if (++s == RING) { s = 0; pph ^= 1; }
        }
    } else if (tid == 0) {
        // -------------------- MMA issue lane --------------------
        int s = 0, fph = 0;
        bool en = false;
        for (int t = 0; t < NST; t++) {
            mbar_wait(su32(&sh_full[s]), (unsigned)fph);
            #pragma unroll
            for (int ks = 0; ks < 4; ks++) {
                unsigned long long o = (unsigned long long)(ks * 2);
                mma_f16_ss(tmem, dxh[s] + o, dbh[s] + o, en); en = true;
                mma_f16_ss(tmem, dxh[s] + o, dbl[s] + o, true);
                mma_f16_ss(tmem, dxl[s] + o, dbh[s] + o, true);
            }
            tc_commit(su32(&sh_empty[s]));
            if (++s == RING) { s = 0; fph ^= 1; }
        }
    }

    // hold early threads (warp0 lanes 1-31) until producers finished
    __syncthreads();

    // stage KAN params while the tail MMAs drain
    float* l1b   = (float*)(base + RING * STG);
    float* wsp   = l1b + 4224;
    float* sbs   = wsp + 5760;
    float* sgrid = sbs + 960;
    float* srden = sgrid + 300;
    kan_stage(tid, g, kan_grid, kan_coef, ksb, ksp, wsp, sbs, sgrid, srden);

    // wait for the LAST stage's commit (same-accumulator MMAs complete in
    // order).  NST%RING==0 -> post-loop producer parity is 1; >=15 of the 16
    // slot-completions have happened by the syncthreads above, so this wait
    // releases exactly on stage NST-1's commit.
    mbar_wait(su32(&sh_empty[(NST - 1) % RING]), 1u);
    asm volatile("tcgen05.fence::after_thread_sync;" ::: "memory");

    const int lid = tid & 31;
    if (wid < 4) {
        unsigned dr[32];
        asm volatile(
            "tcgen05.ld.sync.aligned.32x32b.x32.b32 "
            "{%0,%1,%2,%3,%4,%5,%6,%7,%8,%9,%10,%11,%12,%13,%14,%15,"
            "%16,%17,%18,%19,%20,%21,%22,%23,%24,%25,%26,%27,%28,%29,%30,%31}, [%32];"
            : "=r"(dr[0]), "=r"(dr[1]), "=r"(dr[2]), "=r"(dr[3]),
              "=r"(dr[4]), "=r"(dr[5]), "=r"(dr[6]), "=r"(dr[7]),
              "=r"(dr[8]), "=r"(dr[9]), "=r"(dr[10]), "=r"(dr[11]),
              "=r"(dr[12]), "=r"(dr[13]), "=r"(dr[14]), "=r"(dr[15]),
              "=r"(dr[16]), "=r"(dr[17]), "=r"(dr[18]), "=r"(dr[19]),
              "=r"(dr[20]), "=r"(dr[21]), "=r"(dr[22]), "=r"(dr[23]),
              "=r"(dr[24]), "=r"(dr[25]), "=r"(dr[26]), "=r"(dr[27]),
              "=r"(dr[28]), "=r"(dr[29]), "=r"(dr[30]), "=r"(dr[31])
            : "r"(tmem));
        asm volatile("tcgen05.wait::ld.sync.aligned;" ::: "memory");
        int row = wid * 32 + lid;
        #pragma unroll
        for (int c = 0; c < 32; c++)
            l1b[row * 33 + c] = __uint_as_float(dr[c]) + sh_bias[c];
        asm volatile("tcgen05.fence::before_thread_sync;" ::: "memory");
    }
    __syncthreads();

    if (tid < 256)
        kan_epilogue(tid, g, nrows, l1b, wsp, sbs, sgrid, srden,
                     sh_outw, sh_rows, out_b, out);

    __syncthreads();
    if (tid < 32) {
        asm volatile("tcgen05.dealloc.cta_group::1.sync.aligned.b32 %0, 64;"
                     :: "r"(tmem));
    }

#else
    // ======================= FP32 SIMT fallback (never runs on GB300) ======
    __syncthreads();
    {
    const int tid2 = (tid < 256) ? tid : (tid - 256);   // dup work is benign
    float* xs = (float*)base;            // [128][33]
    float* ws = (float*)base + 4224;     // [32][33]

    const int tx = tid2 & 7;
    const int ty = tid2 >> 3;
    const int wid0 = tid2 >> 5;
    const int wk  = tid2 & 31;

    const float* wptr[4];
    #pragma unroll
    for (int it = 0; it < 4; it++) {
        int c = it * 8 + wid0;
        wptr[it] = (c < 16) ? (l1_w + (size_t)(g * 16 + c) * KD)
                            : (l1f_w + (size_t)(c - 16) * KD);
    }
    const float* xptr[4];
    int xr_[4], xkv[4];
    #pragma unroll
    for (int it = 0; it < 4; it++) {
        int idx = it * 256 + tid2;
        xr_[it] = idx >> 3;
        xkv[it] = idx & 7;
        xptr[it] = x + (size_t)sh_rows[xr_[it]] * KD + xkv[it] * 4;
    }

    float4 xreg[4];
    float  wreg[4];
    #pragma unroll
    for (int it = 0; it < 4; it++) {
        xreg[it] = *(const float4*)(xptr[it]);
        wreg[it] = wptr[it][wk];
    }

    float acc[4][4];
    #pragma unroll
    for (int i = 0; i < 4; i++)
        #pragma unroll
        for (int j = 0; j < 4; j++) acc[i][j] = 0.0f;

    const int NT = KD / 32;
    for (int kt = 0; kt < NT; kt++) {
        __syncthreads();
        #pragma unroll
        for (int it = 0; it < 4; it++) {
            int bofs = xr_[it] * 33 + xkv[it] * 4;
            xs[bofs + 0] = xreg[it].x;  xs[bofs + 1] = xreg[it].y;
            xs[bofs + 2] = xreg[it].z;  xs[bofs + 3] = xreg[it].w;
            ws[(it * 8 + wid0) * 33 + wk] = wreg[it];
        }
        __syncthreads();
        if (kt + 1 < NT) {
            int k0 = (kt + 1) * 32;
            #pragma unroll
            for (int it = 0; it < 4; it++) {
                xreg[it] = *(const float4*)(xptr[it] + k0);
                wreg[it] = wptr[it][k0 + wk];
            }
        }
        #pragma unroll
        for (int kk = 0; kk < 32; kk++) {
            float xv[4], wv[4];
            #pragma unroll
            for (int j = 0; j < 4; j++) {
                xv[j] = xs[(4 * ty + j) * 33 + kk];
                wv[j] = ws[(4 * tx + j) * 33 + kk];
            }
            #pragma unroll
            for (int i = 0; i < 4; i++)
                #pragma unroll
                for (int j = 0; j < 4; j++)
                    acc[i][j] = fmaf(xv[i], wv[j], acc[i][j]);
        }
    }
    __syncthreads();

    #pragma unroll
    for (int i = 0; i < 4; i++)
        #pragma unroll
        for (int j = 0; j < 4; j++)
            xs[(4 * ty + i) * 33 + (4 * tx + j)] = acc[i][j] + sh_bias[4 * tx + j];

    float* l1b   = xs;
    float* wsp   = (float*)base + 4224;
    float* sbs   = wsp + 5760;
    float* sgrid = sbs + 960;
    float* srden = sgrid + 300;
    kan_stage(tid, g, kan_grid, kan_coef, ksb, ksp, wsp, sbs, sgrid, srden);
    __syncthreads();

    if (tid < 256)
        kan_epilogue(tid, g, nrows, l1b, wsp, sbs, sgrid, srden,
                     sh_outw, sh_rows, out_b, out);
    }
#endif
}

// ============================================================================
extern "C" void kernel_launch(void* const* d_in, const int* in_sizes, int n_in,
                              void* d_out, int out_size)
{
    const float* x        = (const float*)d_in[0];
    const int*   ls       = (const int*)  d_in[1];
    const float* l1_w     = (const float*)d_in[2];
    const float* l1_b     = (const float*)d_in[3];
    const float* l1f_w    = (const float*)d_in[4];
    const float* l1f_b    = (const float*)d_in[5];
    const float* kan_grid = (const float*)d_in[6];
    const float* kan_coef = (const float*)d_in[7];
    const float* ksb      = (const float*)d_in[8];
    const float* ksp      = (const float*)d_in[9];
    const float* out_w    = (const float*)d_in[10];
    const float* out_b    = (const float*)d_in[11];
    float* out = (float*)d_out;

    int B = in_sizes[1];

    cudaFuncSetAttribute(k_main, cudaFuncAttributeMaxDynamicSharedMemorySize,
                         ARENA_BYTES);

    int tiles = B / TB + NGRP;   // 136 <= 148 SMs: co-resident (grid barrier)
    k_main<<<tiles, THREADS, ARENA_BYTES>>>(x, ls, l1_w, l1_b, l1f_w, l1f_b,
                                            kan_grid, kan_coef, ksb, ksp,
                                            out_w, out_b, out, B);
}